// round 11
// baseline (speedup 1.0000x reference)
#include <cuda_runtime.h>
#include <cuda_fp16.h>
#include <math.h>

#define Bv  4
#define Nn  24
#define NTT 16
#define TSS 48
#define TT  64
#define THR 384
#define NL  (Nn - 1)          // 23 l-slots per batch
#define NHELP 14              // helpers for l = 0..13
#define HSTART 8              // min width for split
#define SNAN 0x7fc00000u      // Ssc "not ready" sentinel
#define ESCALE 4096.0f
#define EINV   (1.0f / 4096.0f)

typedef unsigned long long u64;

// ---- packed fp32x2 helpers (sm_103a) ----
__device__ __forceinline__ u64 ffma2(u64 a, u64 b, u64 c) {
    u64 d;
    asm("fma.rn.f32x2 %0, %1, %2, %3;" : "=l"(d) : "l"(a), "l"(b), "l"(c));
    return d;
}
__device__ __forceinline__ u64 pack2(float x, float y) {
    u64 d;
    asm("mov.b64 %0, {%1, %2};" : "=l"(d) : "f"(x), "f"(y));
    return d;
}
__device__ __forceinline__ float2 unpack2(u64 v) {
    float2 f;
    asm("mov.b64 {%0, %1}, %2;" : "=f"(f.x), "=f"(f.y) : "l"(v));
    return f;
}

// ---- fast exp: magic-number round + deg-5 Taylor (rel err ~2.4e-6) ----
__device__ __forceinline__ float fexp(float x) {
    x = fmaxf(x, -80.f);
    float k  = fmaf(x, 1.4426950408889634f, 12582912.f);
    int   n  = __float_as_int(k) - 0x4B400000;
    float nf = k - 12582912.f;
    float f  = fmaf(x, 1.4426950408889634f, -nf);
    float p  = 0.0013333558f;
    p = fmaf(p, f, 0.0096181291f);
    p = fmaf(p, f, 0.0555041086f);
    p = fmaf(p, f, 0.2402265069f);
    p = fmaf(p, f, 0.6931471806f);
    p = fmaf(p, f, 1.0f);
    return p * __int_as_float((n + 127) << 23);
}

// ---------------- device scratch ----------------
__device__ __align__(16) __half d_E0h[Bv][Nn][256][NTT];   // exp(R0)*4096, [b][h][sc][a] fp16
__device__ __align__(16) __half d_E1h[Bv][Nn][256][NTT];
__device__ float d_U0t [Bv][Nn][Nn][NTT][NTT];       // [b][h][k][s][a]
__device__ float d_U1t [Bv][Nn][Nn][NTT][NTT];       // [b][h][k][c][a]
__device__ float d_V0t [Bv][Nn][TT][NTT];            // [b][h][c][a]
__device__ float d_V1t [Bv][Nn][TT][NTT];            // [b][h][s][a]
__device__ float d_beta [Bv][Nn+1][Nn+1][NTT][Nn];
__device__ float d_betau[Bv][Nn+1][Nn+1][NTT];
__device__ float d_Ssc  [Bv][Nn+1][Nn+1];
__device__ float d_htmp [Bv][NHELP][Nn+1][NTT][12];  // helper partial tvals, per (b,l,W)
__device__ unsigned d_hflag[Bv][NHELP][Nn+1];        // helper publish flags

// ---------------- kernel 1: rule precompute + flag/sentinel fill ----------------
__global__ void __launch_bounds__(256) k_pre(const float* __restrict__ rule,
                                             const float* __restrict__ unary) {
    int blk = blockIdx.x;
    int h = blk % Nn;
    int a = (blk / Nn) % NTT;
    int b = blk / (Nn * NTT);
    const float2* R2 = (const float2*)(rule + (size_t)((b * NTT + a) * Nn + h) * (TT * TT * 2));

    __shared__ float Er0[TT][TT];
    __shared__ float Er1[TT][TT];
    __shared__ float eus[Nn][49];
    int tid = threadIdx.x;

    if (blk == 0) {  // reset flags/sentinels for this replay (stream-ordered before k_chart)
        for (int i = tid; i < Bv * (Nn + 1) * (Nn + 1); i += 256)
            ((unsigned*)&d_Ssc[0][0][0])[i] = SNAN;
        for (int i = tid; i < Bv * NHELP * (Nn + 1); i += 256)
            ((unsigned*)&d_hflag[0][0][0])[i] = 0u;
    }

    for (int e = tid; e < TT * TT; e += 256) {
        float2 v = R2[e];
        int s = e >> 6, c = e & 63;
        Er0[s][c] = fexp(v.x);
        Er1[s][c] = fexp(v.y);
    }
    for (int t = tid; t < Nn * TSS; t += 256) {
        int k = t / TSS, c = t % TSS;
        eus[k][c] = fexp(unary[(b * Nn + k) * TT + NTT + c]);
    }
    __syncthreads();

    {
        int s = tid >> 4, c = tid & 15;
        d_E0h[b][h][s * 16 + c][a] = __float2half_rn(Er0[s][c] * ESCALE);
        d_E1h[b][h][s * 16 + c][a] = __float2half_rn(Er1[s][c] * ESCALE);
    }
    if (tid < 128) {
        int x = tid & 63;
        float acc = 0.f;
        if (tid < 64) {
            #pragma unroll 8
            for (int s = NTT; s < TT; s++) acc += Er0[s][x];
            d_V0t[b][h][x][a] = acc;
        } else {
            #pragma unroll 8
            for (int c = NTT; c < TT; c++) acc += Er1[x][c];
            d_V1t[b][h][x][a] = acc;
        }
    }
    if (tid < 192) {
        int which = tid / 96;
        int g = tid % 96;
        int x = g & 15, k0 = (g >> 4) * 4;
        float a0 = 0.f, a1 = 0.f, a2 = 0.f, a3 = 0.f;
        if (which == 0) {
            #pragma unroll 8
            for (int c = 0; c < TSS; c++) {
                float e = Er0[x][NTT + c];
                a0 += e * eus[k0 + 0][c];
                a1 += e * eus[k0 + 1][c];
                a2 += e * eus[k0 + 2][c];
                a3 += e * eus[k0 + 3][c];
            }
            d_U0t[b][h][k0 + 0][x][a] = a0;
            d_U0t[b][h][k0 + 1][x][a] = a1;
            d_U0t[b][h][k0 + 2][x][a] = a2;
            d_U0t[b][h][k0 + 3][x][a] = a3;
        } else {
            #pragma unroll 8
            for (int s = 0; s < TSS; s++) {
                float e = Er1[NTT + s][x];
                a0 += e * eus[k0 + 0][s];
                a1 += e * eus[k0 + 1][s];
                a2 += e * eus[k0 + 2][s];
                a3 += e * eus[k0 + 3][s];
            }
            d_U1t[b][h][k0 + 0][x][a] = a0;
            d_U1t[b][h][k0 + 1][x][a] = a1;
            d_U1t[b][h][k0 + 2][x][a] = a2;
            d_U1t[b][h][k0 + 3][x][a] = a3;
        }
    }
}

// spin until Ssc value is published (not sentinel); integer compare = fast-math safe
__device__ __forceinline__ float spin_ssc(const float* p) {
    float v = *(volatile const float*)p;
    while (__float_as_uint(v) == SNAN) {
        __nanosleep(20);
        v = *(volatile const float*)p;
    }
    return v;
}

// ---------------- kernel 2: dataflow chart kernel (owner + helper blocks) ----------------
__global__ void __launch_bounds__(THR, 1) k_chart(const float* __restrict__ unary,
                                                  const float* __restrict__ root,
                                                  float* __restrict__ out) {
    extern __shared__ float dyn[];
    float* P0f  = dyn;                       // [24][264] fp32, row = hh, col = sc
    float* P1f  = dyn + 24 * 264;            // [24][264]
    float* ownB = dyn + 2 * 24 * 264;        // [23][16][24] fp32, slot = width-2
    __shared__ float eu_s[Nn][TT];
    __shared__ __align__(16) float wRTi[NTT][24][2];   // [c][jj]{w0, w1} interleaved
    __shared__ float BL2s[NTT][Nn];
    __shared__ float tmpsm[NTT][Nn];
    __shared__ float ownBu[Nn][NTT];   // slot = width-2
    __shared__ float ownS[Nn + 1];     // own Ssc by width
    __shared__ float wspe[Nn];
    __shared__ float buR0s[NTT];       // wspe[0]   * betau(l+1, r)
    __shared__ float buLW[NTT];        // wspe[W-2] * betau(l, r-1)
    __shared__ float red[12];
    __shared__ float sref_s, Msm_s;

    int tid = threadIdx.x;

    if (blockIdx.x < Bv * NL) {
        // ============================ OWNER ============================
        int b = blockIdx.x / NL;
        int l = blockIdx.x % NL;
        bool hasHelp = (l < NHELP);

        for (int t = tid; t < Nn * TT; t += THR)
            (&eu_s[0][0])[t] = fexp(unary[b * Nn * TT + t]);
        for (int t = tid; t < 8832; t += THR) ownB[t] = 0.f;
        if (tid < 2) ownS[tid] = 0.f;
        __syncthreads();

        int Wmax = Nn - l;
        for (int W = 2; W <= Wmax; W++) {
            int r = l + W;
            int nT = NTT * W;
            int a = tid & 15, hh = tid >> 4;
            bool split = hasHelp && (W >= HSTART);
            int hLim = split ? ((W + 1) >> 1) : W;

            if (W >= 3) {
                // ---- phase 1: warp 0 spins on right children, computes split weights ----
                if (tid < 32) {
                    int j = tid;
                    float v = -1e30f;
                    if (j <= W - 2) {
                        float sl = (j == 0)     ? 0.f : ownS[j + 1];
                        float sr = (j == W - 2) ? 0.f : spin_ssc(&d_Ssc[b][l + 1 + j][r]);
                        v = sl + sr;
                    }
                    __threadfence();   // acquire
                    float mx = v;
                    #pragma unroll
                    for (int o = 16; o > 0; o >>= 1) mx = fmaxf(mx, __shfl_xor_sync(0xffffffffu, mx, o));
                    if (j <= W - 2) wspe[j] = expf(v - mx);
                    if (j == 0) sref_s = mx;
                }
                __syncthreads();

                // ---- phase 2: interleaved weight tables + boundary child data ----
                {
                    int c = tid / 24, jj = tid % 24;   // THR == 16*24
                    int j = jj + 1;
                    bool in = (j <= W - 3);
                    wRTi[c][jj][0] = in ? wspe[j] * __ldcg(&d_betau[b][l + 1 + j][r][c]) : 0.f;
                    wRTi[c][jj][1] = in ? wspe[j] * ownBu[j - 1][c] : 0.f;
                }
                if (tid < NTT * hLim) {
                    int c2 = tid / hLim, h2 = tid % hLim;
                    BL2s[c2][h2] = __ldcg(&d_beta[b][l + 1][r][c2][l + h2]);
                }
                if (tid >= 352) {
                    int c = tid - 352;
                    if (c < NTT) {
                        buR0s[c] = wspe[0] * __ldcg(&d_betau[b][l + 1][r][c]);
                        if (!split) buLW[c] = wspe[W - 2] * ownBu[W - 3][c];
                    }
                }
                __syncthreads();
            } else {
                if (tid == 0) sref_s = 0.f;
                __syncthreads();
            }

            if (W >= 4) {
                // ---- P build (only owner's hh range): FFMA2 fused ----
                if (tid < NTT * hLim) {
                    int phh = tid % hLim, x = tid / hLim;
                    u64 bvp[24];
                    #pragma unroll
                    for (int j = 1; j <= 24; j++) {
                        if (j <= W - 3) {
                            float bl = ownB[(j - 1) * 384 + x * 24 + phh];
                            float br = __ldcg(&d_beta[b][l + 1 + j][r][x][l + phh]);
                            bvp[j - 1] = pack2(bl, br);
                        } else bvp[j - 1] = 0ULL;
                    }
                    #pragma unroll
                    for (int c = 0; c < NTT; c++) {
                        u64 acc = 0ULL;
                        #pragma unroll
                        for (int k = 0; k < 6; k++) {
                            if (4 * k <= W - 4) {   // warp-uniform
                                const u64* wp = reinterpret_cast<const u64*>(&wRTi[c][4 * k][0]);
                                acc = ffma2(bvp[4 * k + 0], wp[0], acc);
                                acc = ffma2(bvp[4 * k + 1], wp[1], acc);
                                acc = ffma2(bvp[4 * k + 2], wp[2], acc);
                                acc = ffma2(bvp[4 * k + 3], wp[3], acc);
                            }
                        }
                        float2 pv = unpack2(acc);
                        P0f[phh * 264 + x * 16 + c] = pv.x;
                        P1f[phh * 264 + c * 16 + x] = pv.y;
                    }
                }
                __syncthreads();

                // ---- contraction (owner's hh range): fp16 E, fp32 accum ----
                {
                    int wd = tid >> 5, lane = tid & 31;
                    int sc_lo = lane >> 1, a8 = lane & 1;
                    for (int chh = wd; chh < hLim; chh += 12) {
                        const uint4* E0 = reinterpret_cast<const uint4*>(&d_E0h[b][l + chh][0][0]);
                        const uint4* E1 = reinterpret_cast<const uint4*>(&d_E1h[b][l + chh][0][0]);
                        const float* p0 = P0f + chh * 264;
                        const float* p1 = P1f + chh * 264;
                        float acc[8];
                        #pragma unroll
                        for (int k = 0; k < 8; k++) acc[k] = 0.f;
                        #pragma unroll
                        for (int i = 0; i < 16; i++) {
                            int sc = i * 16 + sc_lo;
                            float v0 = p0[sc];
                            float v1 = p1[sc];
                            uint4 e0 = __ldg(E0 + sc * 2 + a8);
                            uint4 e1 = __ldg(E1 + sc * 2 + a8);
                            float2 f;
                            f = __half22float2(*reinterpret_cast<const __half2*>(&e0.x));
                            acc[0] = fmaf(v0, f.x, acc[0]); acc[1] = fmaf(v0, f.y, acc[1]);
                            f = __half22float2(*reinterpret_cast<const __half2*>(&e0.y));
                            acc[2] = fmaf(v0, f.x, acc[2]); acc[3] = fmaf(v0, f.y, acc[3]);
                            f = __half22float2(*reinterpret_cast<const __half2*>(&e0.z));
                            acc[4] = fmaf(v0, f.x, acc[4]); acc[5] = fmaf(v0, f.y, acc[5]);
                            f = __half22float2(*reinterpret_cast<const __half2*>(&e0.w));
                            acc[6] = fmaf(v0, f.x, acc[6]); acc[7] = fmaf(v0, f.y, acc[7]);
                            f = __half22float2(*reinterpret_cast<const __half2*>(&e1.x));
                            acc[0] = fmaf(v1, f.x, acc[0]); acc[1] = fmaf(v1, f.y, acc[1]);
                            f = __half22float2(*reinterpret_cast<const __half2*>(&e1.y));
                            acc[2] = fmaf(v1, f.x, acc[2]); acc[3] = fmaf(v1, f.y, acc[3]);
                            f = __half22float2(*reinterpret_cast<const __half2*>(&e1.z));
                            acc[4] = fmaf(v1, f.x, acc[4]); acc[5] = fmaf(v1, f.y, acc[5]);
                            f = __half22float2(*reinterpret_cast<const __half2*>(&e1.w));
                            acc[6] = fmaf(v1, f.x, acc[6]); acc[7] = fmaf(v1, f.y, acc[7]);
                        }
                        #pragma unroll
                        for (int o = 2; o <= 16; o <<= 1) {
                            #pragma unroll
                            for (int k = 0; k < 8; k++)
                                acc[k] += __shfl_xor_sync(0xffffffffu, acc[k], o);
                        }
                        if (sc_lo == 0) {
                            int abase = a8 * 8;
                            #pragma unroll
                            for (int k = 0; k < 8; k++)
                                tmpsm[abase + k][chh] = acc[k] * EINV;
                        }
                    }
                }
                __syncthreads();
            }

            // ---- boundary terms + assemble tval (owner's hh range) ----
            float tval = 0.f;
            if (tid < nT && hh < hLim) {
                if (W >= 3) {
                    if (W >= 4) tval = tmpsm[a][hh];
                    float s2 = 0.f, s3 = 0.f;
                    #pragma unroll
                    for (int c = 0; c < NTT; c++) {
                        s2 += __ldg(&d_U1t[b][l + hh][l][c][a]) * BL2s[c][hh];
                        s3 += __ldg(&d_U0t[b][l + hh][r - 1][c][a]) * ownB[(W - 3) * 384 + c * 24 + hh];
                    }
                    tval += wspe[0] * s2 + wspe[W - 2] * s3;
                    if (hh == 0) {
                        float s1 = 0.f;
                        #pragma unroll
                        for (int c = 0; c < NTT; c++)
                            s1 += __ldg(&d_V0t[b][l][c][a]) * buR0s[c];
                        tval += s1;
                    }
                    if (hh == W - 1) {   // only reachable when !split
                        float s4 = 0.f;
                        #pragma unroll
                        for (int c = 0; c < NTT; c++)
                            s4 += __ldg(&d_V1t[b][r - 1][c][a]) * buLW[c];
                        tval += s4;
                    }
                } else {  // W == 2
                    if (hh == 0) {
                        #pragma unroll 8
                        for (int c = 0; c < TSS; c++)
                            tval += eu_s[l + 1][NTT + c] * __ldg(&d_V0t[b][l][NTT + c][a]);
                    } else {
                        #pragma unroll 8
                        for (int c = 0; c < TSS; c++)
                            tval += eu_s[l][NTT + c] * __ldg(&d_V1t[b][l + 1][NTT + c][a]);
                    }
                }
            }

            // ---- fold in helper's half ----
            if (split) {
                if (tid == 0) {
                    volatile unsigned* fp = &d_hflag[b][l][W];
                    while (*fp == 0u) __nanosleep(20);
                    __threadfence();
                }
                __syncthreads();
                if (tid < nT && hh >= hLim)
                    tval = __ldcg(&d_htmp[b][l][W][a][hh - hLim]);
            }

            // ---- max, rescale, commit, publish (Ssc last = release flag) ----
            float vmax = 0.f;
            if (tid < nT) {
                tmpsm[a][hh] = tval;
                vmax = tval;
            }
            #pragma unroll
            for (int o = 16; o > 0; o >>= 1) vmax = fmaxf(vmax, __shfl_xor_sync(0xffffffffu, vmax, o));
            if ((tid & 31) == 0) red[tid >> 5] = vmax;
            __syncthreads();
            if (tid < 32) {
                float v = (tid < 12) ? red[tid] : 0.f;
                #pragma unroll
                for (int o = 8; o > 0; o >>= 1) v = fmaxf(v, __shfl_xor_sync(0xffffffffu, v, o));
                if (tid == 0) Msm_s = v;
            }
            __syncthreads();
            float invM = 1.f / Msm_s;
            {
                int ca = tid / Nn, habs = tid % Nn;   // THR == 16*24 exactly
                float v = 0.f;
                if (habs >= l && habs < r) {
                    v = tmpsm[ca][habs - l] * invM;
                    ownB[(W - 2) * 384 + ca * 24 + (habs - l)] = v;
                }
                __stcg(&d_beta[b][l][r][ca][habs], v);
            }
            if (tid < NTT) {
                float accu = 0.f;
                for (int h2 = 0; h2 < W; h2++)
                    accu += tmpsm[tid][h2] * eu_s[l + h2][tid];
                float bu = accu * invM;
                __stcg(&d_betau[b][l][r][tid], bu);
                ownBu[W - 2][tid] = bu;
                if (W == Nn) {   // only block (b, 0): fused root reduction
                    float v = bu * __expf(root[b * NTT + tid]);
                    #pragma unroll
                    for (int o = 8; o > 0; o >>= 1) v += __shfl_xor_sync(0xffffu, v, o);
                    if (tid == 0) out[b] = sref_s + logf(Msm_s) + logf(v);
                }
            }
            __threadfence();   // make beta/betau visible before Ssc (the flag)
            __syncthreads();
            if (tid == 0) {
                float ss = sref_s + logf(Msm_s);
                ownS[W] = ss;
                __stcg(&d_Ssc[b][l][r], ss);
            }
            __syncthreads();
        }
    } else {
        // ============================ HELPER ============================
        int hid = blockIdx.x - Bv * NL;
        int b = hid / NHELP;
        int l = hid % NHELP;
        int Wmax = Nn - l;

        for (int W = HSTART; W <= Wmax; W++) {
            int r = l + W;
            int hlo = (W + 1) >> 1;
            int nh = W - hlo;

            // ---- phase 1: spin on ALL children (both sides), compute split weights ----
            if (tid < 32) {
                int j = tid;
                float v = -1e30f;
                if (j <= W - 2) {
                    float sl = (j == 0)     ? 0.f : spin_ssc(&d_Ssc[b][l][l + 1 + j]);
                    float sr = (j == W - 2) ? 0.f : spin_ssc(&d_Ssc[b][l + 1 + j][r]);
                    v = sl + sr;
                }
                __threadfence();   // acquire
                float mx = v;
                #pragma unroll
                for (int o = 16; o > 0; o >>= 1) mx = fmaxf(mx, __shfl_xor_sync(0xffffffffu, mx, o));
                if (j <= W - 2) wspe[j] = expf(v - mx);
            }
            __syncthreads();

            // ---- phase 2: weight tables from global chart ----
            {
                int c = tid / 24, jj = tid % 24;
                int j = jj + 1;
                bool in = (j <= W - 3);
                wRTi[c][jj][0] = in ? wspe[j] * __ldcg(&d_betau[b][l + 1 + j][r][c]) : 0.f;
                wRTi[c][jj][1] = in ? wspe[j] * __ldcg(&d_betau[b][l][l + 1 + j][c]) : 0.f;
            }
            if (tid >= 352) {
                int c = tid - 352;
                if (c < NTT) buLW[c] = wspe[W - 2] * __ldcg(&d_betau[b][l][r - 1][c]);
            }
            __syncthreads();

            // ---- P build for hh in [hlo, W) ----
            if (tid < NTT * nh) {
                int phh = tid % nh + hlo, x = tid / nh;
                u64 bvp[24];
                #pragma unroll
                for (int j = 1; j <= 24; j++) {
                    if (j <= W - 3) {
                        float bl = __ldcg(&d_beta[b][l][l + 1 + j][x][l + phh]);
                        float br = __ldcg(&d_beta[b][l + 1 + j][r][x][l + phh]);
                        bvp[j - 1] = pack2(bl, br);
                    } else bvp[j - 1] = 0ULL;
                }
                #pragma unroll
                for (int c = 0; c < NTT; c++) {
                    u64 acc = 0ULL;
                    #pragma unroll
                    for (int k = 0; k < 6; k++) {
                        if (4 * k <= W - 4) {   // warp-uniform
                            const u64* wp = reinterpret_cast<const u64*>(&wRTi[c][4 * k][0]);
                            acc = ffma2(bvp[4 * k + 0], wp[0], acc);
                            acc = ffma2(bvp[4 * k + 1], wp[1], acc);
                            acc = ffma2(bvp[4 * k + 2], wp[2], acc);
                            acc = ffma2(bvp[4 * k + 3], wp[3], acc);
                        }
                    }
                    float2 pv = unpack2(acc);
                    P0f[phh * 264 + x * 16 + c] = pv.x;
                    P1f[phh * 264 + c * 16 + x] = pv.y;
                }
            }
            __syncthreads();

            // ---- contraction for hh in [hlo, W) ----
            {
                int wd = tid >> 5, lane = tid & 31;
                int sc_lo = lane >> 1, a8 = lane & 1;
                for (int chh = hlo + wd; chh < W; chh += 12) {
                    const uint4* E0 = reinterpret_cast<const uint4*>(&d_E0h[b][l + chh][0][0]);
                    const uint4* E1 = reinterpret_cast<const uint4*>(&d_E1h[b][l + chh][0][0]);
                    const float* p0 = P0f + chh * 264;
                    const float* p1 = P1f + chh * 264;
                    float acc[8];
                    #pragma unroll
                    for (int k = 0; k < 8; k++) acc[k] = 0.f;
                    #pragma unroll
                    for (int i = 0; i < 16; i++) {
                        int sc = i * 16 + sc_lo;
                        float v0 = p0[sc];
                        float v1 = p1[sc];
                        uint4 e0 = __ldg(E0 + sc * 2 + a8);
                        uint4 e1 = __ldg(E1 + sc * 2 + a8);
                        float2 f;
                        f = __half22float2(*reinterpret_cast<const __half2*>(&e0.x));
                        acc[0] = fmaf(v0, f.x, acc[0]); acc[1] = fmaf(v0, f.y, acc[1]);
                        f = __half22float2(*reinterpret_cast<const __half2*>(&e0.y));
                        acc[2] = fmaf(v0, f.x, acc[2]); acc[3] = fmaf(v0, f.y, acc[3]);
                        f = __half22float2(*reinterpret_cast<const __half2*>(&e0.z));
                        acc[4] = fmaf(v0, f.x, acc[4]); acc[5] = fmaf(v0, f.y, acc[5]);
                        f = __half22float2(*reinterpret_cast<const __half2*>(&e0.w));
                        acc[6] = fmaf(v0, f.x, acc[6]); acc[7] = fmaf(v0, f.y, acc[7]);
                        f = __half22float2(*reinterpret_cast<const __half2*>(&e1.x));
                        acc[0] = fmaf(v1, f.x, acc[0]); acc[1] = fmaf(v1, f.y, acc[1]);
                        f = __half22float2(*reinterpret_cast<const __half2*>(&e1.y));
                        acc[2] = fmaf(v1, f.x, acc[2]); acc[3] = fmaf(v1, f.y, acc[3]);
                        f = __half22float2(*reinterpret_cast<const __half2*>(&e1.z));
                        acc[4] = fmaf(v1, f.x, acc[4]); acc[5] = fmaf(v1, f.y, acc[5]);
                        f = __half22float2(*reinterpret_cast<const __half2*>(&e1.w));
                        acc[6] = fmaf(v1, f.x, acc[6]); acc[7] = fmaf(v1, f.y, acc[7]);
                    }
                    #pragma unroll
                    for (int o = 2; o <= 16; o <<= 1) {
                        #pragma unroll
                        for (int k = 0; k < 8; k++)
                            acc[k] += __shfl_xor_sync(0xffffffffu, acc[k], o);
                    }
                    if (sc_lo == 0) {
                        int abase = a8 * 8;
                        #pragma unroll
                        for (int k = 0; k < 8; k++)
                            tmpsm[abase + k][chh] = acc[k] * EINV;
                    }
                }
            }
            __syncthreads();

            // ---- boundary + publish ----
            {
                int a2 = tid & 15, hx = tid >> 4;
                if (hx < nh) {
                    int hh = hlo + hx;
                    float tv = tmpsm[a2][hh];
                    float s2 = 0.f, s3 = 0.f;
                    #pragma unroll
                    for (int c = 0; c < NTT; c++) {
                        s2 += __ldg(&d_U1t[b][l + hh][l][c][a2]) * __ldcg(&d_beta[b][l + 1][r][c][l + hh]);
                        s3 += __ldg(&d_U0t[b][l + hh][r - 1][c][a2]) * __ldcg(&d_beta[b][l][r - 1][c][l + hh]);
                    }
                    tv += wspe[0] * s2 + wspe[W - 2] * s3;
                    if (hh == W - 1) {
                        float s4 = 0.f;
                        #pragma unroll
                        for (int c = 0; c < NTT; c++)
                            s4 += __ldg(&d_V1t[b][r - 1][c][a2]) * buLW[c];
                        tv += s4;
                    }
                    __stcg(&d_htmp[b][l][W][a2][hx], tv);
                }
            }
            __threadfence();
            __syncthreads();
            if (tid == 0) *((volatile unsigned*)&d_hflag[b][l][W]) = 1u;
        }
    }
}

// ---------------- launch ----------------
extern "C" void kernel_launch(void* const* d_in, const int* in_sizes, int n_in,
                              void* d_out, int out_size) {
    const float* unary = nullptr;
    const float* rule  = nullptr;
    const float* root  = nullptr;
    for (int i = 0; i < n_in; i++) {
        if (in_sizes[i] == Bv * Nn * TT)                      unary = (const float*)d_in[i];
        else if (in_sizes[i] == Bv * NTT * Nn * TT * TT * 2)  rule  = (const float*)d_in[i];
        else if (in_sizes[i] == Bv * NTT)                     root  = (const float*)d_in[i];
    }

    int dynBytes = (2 * 24 * 264 + 23 * 16 * 24) * (int)sizeof(float);  // 86016
    cudaFuncSetAttribute(k_chart, cudaFuncAttributeMaxDynamicSharedMemorySize, dynBytes);

    k_pre<<<Bv * NTT * Nn, 256>>>(rule, unary);
    k_chart<<<Bv * NL + Bv * NHELP, THR, dynBytes>>>(unary, root, (float*)d_out);
}

// round 12
// speedup vs baseline: 1.1678x; 1.1678x over previous
#include <cuda_runtime.h>
#include <cuda_fp16.h>
#include <math.h>

#define Bv  4
#define Nn  24
#define NTT 16
#define TSS 48
#define TT  64
#define THR 384
#define NL  (Nn - 1)          // 23 l-slots per batch
#define SNAN 0x7fc00000u      // Ssc "not ready" sentinel
#define ESCALE 4096.0f
#define EINV   (1.0f / 4096.0f)

typedef unsigned long long u64;

// ---- packed fp32x2 helpers (sm_103a) ----
__device__ __forceinline__ u64 ffma2(u64 a, u64 b, u64 c) {
    u64 d;
    asm("fma.rn.f32x2 %0, %1, %2, %3;" : "=l"(d) : "l"(a), "l"(b), "l"(c));
    return d;
}
__device__ __forceinline__ u64 pack2(float x, float y) {
    u64 d;
    asm("mov.b64 %0, {%1, %2};" : "=l"(d) : "f"(x), "f"(y));
    return d;
}
__device__ __forceinline__ float2 unpack2(u64 v) {
    float2 f;
    asm("mov.b64 {%0, %1}, %2;" : "=f"(f.x), "=f"(f.y) : "l"(v));
    return f;
}

// ---- fast exp: magic-number round + deg-5 Taylor (rel err ~2.4e-6) ----
__device__ __forceinline__ float fexp(float x) {
    x = fmaxf(x, -80.f);
    float k  = fmaf(x, 1.4426950408889634f, 12582912.f);
    int   n  = __float_as_int(k) - 0x4B400000;
    float nf = k - 12582912.f;
    float f  = fmaf(x, 1.4426950408889634f, -nf);
    float p  = 0.0013333558f;
    p = fmaf(p, f, 0.0096181291f);
    p = fmaf(p, f, 0.0555041086f);
    p = fmaf(p, f, 0.2402265069f);
    p = fmaf(p, f, 0.6931471806f);
    p = fmaf(p, f, 1.0f);
    return p * __int_as_float((n + 127) << 23);
}

// ---------------- device scratch ----------------
__device__ __align__(16) __half d_E0h[Bv][Nn][256][NTT];   // exp(R0)*4096, [b][h][sc][a] fp16
__device__ __align__(16) __half d_E1h[Bv][Nn][256][NTT];
__device__ __align__(16) float d_U0t [Bv][Nn][Nn][NTT][NTT];  // [b][h][k][s][a]
__device__ __align__(16) float d_U1t [Bv][Nn][Nn][NTT][NTT];  // [b][h][k][c][a]
__device__ __align__(16) float d_V0t [Bv][Nn][TT][NTT];       // [b][h][c][a]
__device__ __align__(16) float d_V1t [Bv][Nn][TT][NTT];       // [b][h][s][a]
__device__ float d_beta [Bv][Nn+1][Nn+1][NTT][Nn];
__device__ float d_betau[Bv][Nn+1][Nn+1][NTT];
__device__ float d_Ssc  [Bv][Nn+1][Nn+1];

// ---------------- kernel 1: rule precompute + Ssc sentinel fill ----------------
__global__ void __launch_bounds__(256) k_pre(const float* __restrict__ rule,
                                             const float* __restrict__ unary) {
    int blk = blockIdx.x;
    int h = blk % Nn;
    int a = (blk / Nn) % NTT;
    int b = blk / (Nn * NTT);
    const float2* R2 = (const float2*)(rule + (size_t)((b * NTT + a) * Nn + h) * (TT * TT * 2));

    __shared__ float Er0[TT][65];   // padded: kills 16-way LDS conflict in U loops
    __shared__ float Er1[TT][65];
    __shared__ float eus[Nn][49];
    int tid = threadIdx.x;

    if (blk == 0) {  // sentinel-fill Ssc (doubles as dataflow flag); stream-ordered before k_chart
        for (int i = tid; i < Bv * (Nn + 1) * (Nn + 1); i += 256)
            ((unsigned*)&d_Ssc[0][0][0])[i] = SNAN;
    }

    for (int e = tid; e < TT * TT; e += 256) {
        float2 v = R2[e];
        int s = e >> 6, c = e & 63;
        Er0[s][c] = fexp(v.x);
        Er1[s][c] = fexp(v.y);
    }
    for (int t = tid; t < Nn * TSS; t += 256) {
        int k = t / TSS, c = t % TSS;
        eus[k][c] = fexp(unary[(b * Nn + k) * TT + NTT + c]);
    }
    __syncthreads();

    {
        int s = tid >> 4, c = tid & 15;
        d_E0h[b][h][s * 16 + c][a] = __float2half_rn(Er0[s][c] * ESCALE);
        d_E1h[b][h][s * 16 + c][a] = __float2half_rn(Er1[s][c] * ESCALE);
    }
    if (tid < 128) {
        int x = tid & 63;
        float acc = 0.f;
        if (tid < 64) {
            #pragma unroll 8
            for (int s = NTT; s < TT; s++) acc += Er0[s][x];
            d_V0t[b][h][x][a] = acc;
        } else {
            #pragma unroll 8
            for (int c = NTT; c < TT; c++) acc += Er1[x][c];
            d_V1t[b][h][x][a] = acc;
        }
    }
    if (tid < 192) {
        int which = tid / 96;
        int g = tid % 96;
        int x = g & 15, k0 = (g >> 4) * 4;
        float a0 = 0.f, a1 = 0.f, a2 = 0.f, a3 = 0.f;
        if (which == 0) {
            #pragma unroll 8
            for (int c = 0; c < TSS; c++) {
                float e = Er0[x][NTT + c];
                a0 += e * eus[k0 + 0][c];
                a1 += e * eus[k0 + 1][c];
                a2 += e * eus[k0 + 2][c];
                a3 += e * eus[k0 + 3][c];
            }
            d_U0t[b][h][k0 + 0][x][a] = a0;
            d_U0t[b][h][k0 + 1][x][a] = a1;
            d_U0t[b][h][k0 + 2][x][a] = a2;
            d_U0t[b][h][k0 + 3][x][a] = a3;
        } else {
            #pragma unroll 8
            for (int s = 0; s < TSS; s++) {
                float e = Er1[NTT + s][x];
                a0 += e * eus[k0 + 0][s];
                a1 += e * eus[k0 + 1][s];
                a2 += e * eus[k0 + 2][s];
                a3 += e * eus[k0 + 3][s];
            }
            d_U1t[b][h][k0 + 0][x][a] = a0;
            d_U1t[b][h][k0 + 1][x][a] = a1;
            d_U1t[b][h][k0 + 2][x][a] = a2;
            d_U1t[b][h][k0 + 3][x][a] = a3;
        }
    }
}

// spin until Ssc value is published (not sentinel); integer compare = fast-math safe
__device__ __forceinline__ float spin_ssc(const float* p) {
    float v = *(volatile const float*)p;
    while (__float_as_uint(v) == SNAN) {
        __nanosleep(20);
        v = *(volatile const float*)p;
    }
    return v;
}

// ---------------- kernel 2: dataflow chart kernel ----------------
__global__ void __launch_bounds__(THR, 1) k_chart(const float* __restrict__ unary,
                                                  const float* __restrict__ root,
                                                  float* __restrict__ out) {
    extern __shared__ float dyn[];
    float* P0f  = dyn;                       // [24][264] fp32, row = hh, col = sc
    float* P1f  = dyn + 24 * 264;            // [24][264]
    float* ownB = dyn + 2 * 24 * 264;        // [23][16][24] fp32, slot = width-2
    __shared__ float eu_s[Nn][TT];
    __shared__ __align__(16) float wRTi[NTT][24][2];   // [c][jj]{w0, w1} interleaved
    __shared__ float BL2s[NTT][Nn];
    __shared__ float tmpsm[NTT][Nn];
    __shared__ float ownBu[Nn][NTT];   // slot = width-2
    __shared__ float ownS[Nn + 1];     // own Ssc by width
    __shared__ float wspe[Nn];
    __shared__ float buR0s[NTT];       // wspe[0]   * betau(l+1, r)
    __shared__ float buLW[NTT];        // wspe[W-2] * ownBu(l, r-1)
    __shared__ float red[12];
    __shared__ float sref_s, Msm_s;

    int tid = threadIdx.x;
    int b = blockIdx.x / NL;
    int l = blockIdx.x % NL;

    for (int t = tid; t < Nn * TT; t += THR)
        (&eu_s[0][0])[t] = fexp(unary[b * Nn * TT + t]);
    for (int t = tid; t < 8832; t += THR) ownB[t] = 0.f;
    if (tid < 2) ownS[tid] = 0.f;
    __syncthreads();

    int Wmax = Nn - l;
    for (int W = 2; W <= Wmax; W++) {
        int r = l + W;
        int nT = NTT * W;
        int a = tid & 15, hh = tid >> 4;

        if (W >= 3) {
            // ---- phase 1: warp 0 spins on right children, computes split weights ----
            if (tid < 32) {
                __syncwarp();   // order vs lane-0's ownS write last iteration
                int j = tid;
                float v = -1e30f;
                if (j <= W - 2) {
                    float sl = (j == 0)     ? 0.f : ownS[j + 1];
                    float sr = (j == W - 2) ? 0.f : spin_ssc(&d_Ssc[b][l + 1 + j][r]);
                    v = sl + sr;
                }
                __threadfence();   // acquire
                float mx = v;
                #pragma unroll
                for (int o = 16; o > 0; o >>= 1) mx = fmaxf(mx, __shfl_xor_sync(0xffffffffu, mx, o));
                if (j <= W - 2) wspe[j] = expf(v - mx);
                if (j == 0) sref_s = mx;
            }
            __syncthreads();

            // ---- phase 2: interleaved weight tables + boundary child data ----
            {
                int c = tid / 24, jj = tid % 24;   // THR == 16*24
                int j = jj + 1;
                bool in = (j <= W - 3);
                wRTi[c][jj][0] = in ? wspe[j] * __ldcg(&d_betau[b][l + 1 + j][r][c]) : 0.f;
                wRTi[c][jj][1] = in ? wspe[j] * ownBu[j - 1][c] : 0.f;
            }
            if (tid < nT) {
                int c2 = tid / W, h2 = tid % W;
                BL2s[c2][h2] = __ldcg(&d_beta[b][l + 1][r][c2][l + h2]);
            }
            if (tid >= 352) {
                int c = tid - 352;
                if (c < NTT) {
                    buR0s[c] = wspe[0] * __ldcg(&d_betau[b][l + 1][r][c]);
                    buLW[c]  = wspe[W - 2] * ownBu[W - 3][c];
                }
            }
            __syncthreads();
        } else {
            if (tid == 0) sref_s = 0.f;
            __syncthreads();
        }

        if (W >= 4) {
            // ---- P build: both tables fused via FFMA2 ----
            if (tid < nT) {
                int phh = tid % W, x = tid / W;
                u64 bvp[24];
                #pragma unroll
                for (int j = 1; j <= 24; j++) {
                    if (j <= W - 3) {
                        float bl = ownB[(j - 1) * 384 + x * 24 + phh];
                        float br = __ldcg(&d_beta[b][l + 1 + j][r][x][l + phh]);
                        bvp[j - 1] = pack2(bl, br);
                    } else bvp[j - 1] = 0ULL;
                }
                #pragma unroll
                for (int c = 0; c < NTT; c++) {
                    u64 acc = 0ULL;
                    #pragma unroll
                    for (int k = 0; k < 6; k++) {
                        if (4 * k <= W - 4) {   // warp-uniform
                            const u64* wp = reinterpret_cast<const u64*>(&wRTi[c][4 * k][0]);
                            acc = ffma2(bvp[4 * k + 0], wp[0], acc);
                            acc = ffma2(bvp[4 * k + 1], wp[1], acc);
                            acc = ffma2(bvp[4 * k + 2], wp[2], acc);
                            acc = ffma2(bvp[4 * k + 3], wp[3], acc);
                        }
                    }
                    float2 pv = unpack2(acc);
                    P0f[phh * 264 + x * 16 + c] = pv.x;
                    P1f[phh * 264 + c * 16 + x] = pv.y;
                }
            }
            __syncthreads();

            // ---- contraction + folded boundary: warp per hh; lanes = (sc_lo 16, a8 2) ----
            {
                int wd = tid >> 5, lane = tid & 31;
                int sc_lo = lane >> 1, a8 = lane & 1;
                float wspe0  = wspe[0];
                float wspeW2 = wspe[W - 2];
                for (int chh = wd; chh < W; chh += 12) {
                    const uint4* E0 = reinterpret_cast<const uint4*>(&d_E0h[b][l + chh][0][0]);
                    const uint4* E1 = reinterpret_cast<const uint4*>(&d_E1h[b][l + chh][0][0]);
                    const float* p0 = P0f + chh * 264;
                    const float* p1 = P1f + chh * 264;
                    float acc[8];
                    #pragma unroll
                    for (int k = 0; k < 8; k++) acc[k] = 0.f;
                    #pragma unroll
                    for (int i = 0; i < 16; i++) {
                        int sc = i * 16 + sc_lo;
                        float v0 = p0[sc];
                        float v1 = p1[sc];
                        uint4 e0 = __ldg(E0 + sc * 2 + a8);
                        uint4 e1 = __ldg(E1 + sc * 2 + a8);
                        float2 f;
                        f = __half22float2(*reinterpret_cast<const __half2*>(&e0.x));
                        acc[0] = fmaf(v0, f.x, acc[0]); acc[1] = fmaf(v0, f.y, acc[1]);
                        f = __half22float2(*reinterpret_cast<const __half2*>(&e0.y));
                        acc[2] = fmaf(v0, f.x, acc[2]); acc[3] = fmaf(v0, f.y, acc[3]);
                        f = __half22float2(*reinterpret_cast<const __half2*>(&e0.z));
                        acc[4] = fmaf(v0, f.x, acc[4]); acc[5] = fmaf(v0, f.y, acc[5]);
                        f = __half22float2(*reinterpret_cast<const __half2*>(&e0.w));
                        acc[6] = fmaf(v0, f.x, acc[6]); acc[7] = fmaf(v0, f.y, acc[7]);
                        f = __half22float2(*reinterpret_cast<const __half2*>(&e1.x));
                        acc[0] = fmaf(v1, f.x, acc[0]); acc[1] = fmaf(v1, f.y, acc[1]);
                        f = __half22float2(*reinterpret_cast<const __half2*>(&e1.y));
                        acc[2] = fmaf(v1, f.x, acc[2]); acc[3] = fmaf(v1, f.y, acc[3]);
                        f = __half22float2(*reinterpret_cast<const __half2*>(&e1.z));
                        acc[4] = fmaf(v1, f.x, acc[4]); acc[5] = fmaf(v1, f.y, acc[5]);
                        f = __half22float2(*reinterpret_cast<const __half2*>(&e1.w));
                        acc[6] = fmaf(v1, f.x, acc[6]); acc[7] = fmaf(v1, f.y, acc[7]);
                    }
                    // folded boundary terms (fp32 tables, weights pre-scaled by ESCALE)
                    {   // s2: U1(l+hh, k=l) . (wspe0 * BL2)
                        float v = wspe0 * ESCALE * BL2s[sc_lo][chh];
                        const float4* U1 = reinterpret_cast<const float4*>(
                            &d_U1t[b][l + chh][l][sc_lo][a8 * 8]);
                        float4 ua = __ldg(U1), ub = __ldg(U1 + 1);
                        acc[0] = fmaf(v, ua.x, acc[0]); acc[1] = fmaf(v, ua.y, acc[1]);
                        acc[2] = fmaf(v, ua.z, acc[2]); acc[3] = fmaf(v, ua.w, acc[3]);
                        acc[4] = fmaf(v, ub.x, acc[4]); acc[5] = fmaf(v, ub.y, acc[5]);
                        acc[6] = fmaf(v, ub.z, acc[6]); acc[7] = fmaf(v, ub.w, acc[7]);
                    }
                    {   // s3: U0(l+hh, k=r-1) . (wspeW2 * ownB(l, r-1))
                        float v = wspeW2 * ESCALE * ownB[(W - 3) * 384 + sc_lo * 24 + chh];
                        const float4* U0 = reinterpret_cast<const float4*>(
                            &d_U0t[b][l + chh][r - 1][sc_lo][a8 * 8]);
                        float4 ua = __ldg(U0), ub = __ldg(U0 + 1);
                        acc[0] = fmaf(v, ua.x, acc[0]); acc[1] = fmaf(v, ua.y, acc[1]);
                        acc[2] = fmaf(v, ua.z, acc[2]); acc[3] = fmaf(v, ua.w, acc[3]);
                        acc[4] = fmaf(v, ub.x, acc[4]); acc[5] = fmaf(v, ub.y, acc[5]);
                        acc[6] = fmaf(v, ub.z, acc[6]); acc[7] = fmaf(v, ub.w, acc[7]);
                    }
                    if (chh == 0) {   // s1: V0(l) . buR0s
                        float v = ESCALE * buR0s[sc_lo];
                        const float4* V0 = reinterpret_cast<const float4*>(
                            &d_V0t[b][l][sc_lo][a8 * 8]);
                        float4 ua = __ldg(V0), ub = __ldg(V0 + 1);
                        acc[0] = fmaf(v, ua.x, acc[0]); acc[1] = fmaf(v, ua.y, acc[1]);
                        acc[2] = fmaf(v, ua.z, acc[2]); acc[3] = fmaf(v, ua.w, acc[3]);
                        acc[4] = fmaf(v, ub.x, acc[4]); acc[5] = fmaf(v, ub.y, acc[5]);
                        acc[6] = fmaf(v, ub.z, acc[6]); acc[7] = fmaf(v, ub.w, acc[7]);
                    }
                    if (chh == W - 1) {   // s4: V1(r-1) . buLW
                        float v = ESCALE * buLW[sc_lo];
                        const float4* V1 = reinterpret_cast<const float4*>(
                            &d_V1t[b][r - 1][sc_lo][a8 * 8]);
                        float4 ua = __ldg(V1), ub = __ldg(V1 + 1);
                        acc[0] = fmaf(v, ua.x, acc[0]); acc[1] = fmaf(v, ua.y, acc[1]);
                        acc[2] = fmaf(v, ua.z, acc[2]); acc[3] = fmaf(v, ua.w, acc[3]);
                        acc[4] = fmaf(v, ub.x, acc[4]); acc[5] = fmaf(v, ub.y, acc[5]);
                        acc[6] = fmaf(v, ub.z, acc[6]); acc[7] = fmaf(v, ub.w, acc[7]);
                    }
                    #pragma unroll
                    for (int o = 2; o <= 16; o <<= 1) {
                        #pragma unroll
                        for (int k = 0; k < 8; k++)
                            acc[k] += __shfl_xor_sync(0xffffffffu, acc[k], o);
                    }
                    if (sc_lo == 0) {
                        int abase = a8 * 8;
                        #pragma unroll
                        for (int k = 0; k < 8; k++)
                            tmpsm[abase + k][chh] = acc[k] * EINV;   // final tval
                    }
                }
            }
            __syncthreads();
        } else {
            // ---- W == 2 / 3: small direct paths write tmpsm ----
            float tval = 0.f;
            if (tid < nT) {
                if (W == 3) {
                    float s2 = 0.f, s3 = 0.f;
                    #pragma unroll
                    for (int c = 0; c < NTT; c++) {
                        s2 += __ldg(&d_U1t[b][l + hh][l][c][a]) * BL2s[c][hh];
                        s3 += __ldg(&d_U0t[b][l + hh][r - 1][c][a]) * ownB[(W - 3) * 384 + c * 24 + hh];
                    }
                    tval = wspe[0] * s2 + wspe[W - 2] * s3;
                    if (hh == 0) {
                        float s1 = 0.f;
                        #pragma unroll
                        for (int c = 0; c < NTT; c++)
                            s1 += __ldg(&d_V0t[b][l][c][a]) * buR0s[c];
                        tval += s1;
                    }
                    if (hh == W - 1) {
                        float s4 = 0.f;
                        #pragma unroll
                        for (int c = 0; c < NTT; c++)
                            s4 += __ldg(&d_V1t[b][r - 1][c][a]) * buLW[c];
                        tval += s4;
                    }
                } else {  // W == 2
                    if (hh == 0) {
                        #pragma unroll 8
                        for (int c = 0; c < TSS; c++)
                            tval += eu_s[l + 1][NTT + c] * __ldg(&d_V0t[b][l][NTT + c][a]);
                    } else {
                        #pragma unroll 8
                        for (int c = 0; c < TSS; c++)
                            tval += eu_s[l][NTT + c] * __ldg(&d_V1t[b][l + 1][NTT + c][a]);
                    }
                }
                tmpsm[a][hh] = tval;
            }
            __syncthreads();
        }

        // ---- max, rescale, commit, publish (Ssc last = release flag) ----
        float vmax = (tid < nT) ? tmpsm[a][hh] : 0.f;
        #pragma unroll
        for (int o = 16; o > 0; o >>= 1) vmax = fmaxf(vmax, __shfl_xor_sync(0xffffffffu, vmax, o));
        if ((tid & 31) == 0) red[tid >> 5] = vmax;
        __syncthreads();
        if (tid < 32) {
            float v = (tid < 12) ? red[tid] : 0.f;
            #pragma unroll
            for (int o = 8; o > 0; o >>= 1) v = fmaxf(v, __shfl_xor_sync(0xffffffffu, v, o));
            if (tid == 0) Msm_s = v;
        }
        __syncthreads();
        float invM = 1.f / Msm_s;
        {
            int ca = tid / Nn, habs = tid % Nn;   // THR == 16*24 exactly
            float v = 0.f;
            if (habs >= l && habs < r) {
                v = tmpsm[ca][habs - l] * invM;
                ownB[(W - 2) * 384 + ca * 24 + (habs - l)] = v;
            }
            __stcg(&d_beta[b][l][r][ca][habs], v);
        }
        if (tid < NTT) {
            float accu = 0.f;
            for (int h2 = 0; h2 < W; h2++)
                accu += tmpsm[tid][h2] * eu_s[l + h2][tid];
            float bu = accu * invM;
            __stcg(&d_betau[b][l][r][tid], bu);
            ownBu[W - 2][tid] = bu;
            if (W == Nn) {   // only block (b, 0): fused root reduction
                float v = bu * __expf(root[b * NTT + tid]);
                #pragma unroll
                for (int o = 8; o > 0; o >>= 1) v += __shfl_xor_sync(0xffffu, v, o);
                if (tid == 0) out[b] = sref_s + logf(Msm_s) + logf(v);
            }
        }
        __threadfence();   // make beta/betau visible before Ssc (the flag)
        __syncthreads();
        if (tid == 0) {
            float ss = sref_s + logf(Msm_s);
            ownS[W] = ss;
            __stcg(&d_Ssc[b][l][r], ss);
        }
        // no trailing sync: next phase uses __syncwarp (warp 0) / phase-1 barrier
    }
}

// ---------------- launch ----------------
extern "C" void kernel_launch(void* const* d_in, const int* in_sizes, int n_in,
                              void* d_out, int out_size) {
    const float* unary = nullptr;
    const float* rule  = nullptr;
    const float* root  = nullptr;
    for (int i = 0; i < n_in; i++) {
        if (in_sizes[i] == Bv * Nn * TT)                      unary = (const float*)d_in[i];
        else if (in_sizes[i] == Bv * NTT * Nn * TT * TT * 2)  rule  = (const float*)d_in[i];
        else if (in_sizes[i] == Bv * NTT)                     root  = (const float*)d_in[i];
    }

    int dynBytes = (2 * 24 * 264 + 23 * 16 * 24) * (int)sizeof(float);  // 86016
    cudaFuncSetAttribute(k_chart, cudaFuncAttributeMaxDynamicSharedMemorySize, dynBytes);

    k_pre<<<Bv * NTT * Nn, 256>>>(rule, unary);
    k_chart<<<Bv * NL, THR, dynBytes>>>(unary, root, (float*)d_out);
}

// round 13
// speedup vs baseline: 1.2035x; 1.0305x over previous
#include <cuda_runtime.h>
#include <cuda_fp16.h>
#include <math.h>

#define Bv  4
#define Nn  24
#define NTT 16
#define TSS 48
#define TT  64
#define THR 384
#define NL  (Nn - 1)          // 23 l-slots per batch
#define SNAN 0x7fc00000u      // Ssc "not ready" sentinel
#define ESCALE 4096.0f
#define EINV   (1.0f / 4096.0f)

typedef unsigned long long u64;

// ---- packed fp32x2 helpers (sm_103a) ----
__device__ __forceinline__ u64 ffma2(u64 a, u64 b, u64 c) {
    u64 d;
    asm("fma.rn.f32x2 %0, %1, %2, %3;" : "=l"(d) : "l"(a), "l"(b), "l"(c));
    return d;
}
__device__ __forceinline__ u64 pack2(float x, float y) {
    u64 d;
    asm("mov.b64 %0, {%1, %2};" : "=l"(d) : "f"(x), "f"(y));
    return d;
}
__device__ __forceinline__ float2 unpack2(u64 v) {
    float2 f;
    asm("mov.b64 {%0, %1}, %2;" : "=f"(f.x), "=f"(f.y) : "l"(v));
    return f;
}

// ---- fast exp: magic-number round + deg-5 Taylor (rel err ~2.4e-6) ----
__device__ __forceinline__ float fexp(float x) {
    x = fmaxf(x, -80.f);
    float k  = fmaf(x, 1.4426950408889634f, 12582912.f);
    int   n  = __float_as_int(k) - 0x4B400000;
    float nf = k - 12582912.f;
    float f  = fmaf(x, 1.4426950408889634f, -nf);
    float p  = 0.0013333558f;
    p = fmaf(p, f, 0.0096181291f);
    p = fmaf(p, f, 0.0555041086f);
    p = fmaf(p, f, 0.2402265069f);
    p = fmaf(p, f, 0.6931471806f);
    p = fmaf(p, f, 1.0f);
    return p * __int_as_float((n + 127) << 23);
}

// ---- release/acquire publish primitives (GPU scope, cumulative) ----
__device__ __forceinline__ void st_release_gpu(float* p, float v) {
    asm volatile("st.release.gpu.global.b32 [%0], %1;" :: "l"(p), "f"(v) : "memory");
}
__device__ __forceinline__ float ld_acquire_gpu(const float* p) {
    float v;
    asm volatile("ld.acquire.gpu.global.b32 %0, [%1];" : "=f"(v) : "l"(p) : "memory");
    return v;
}

// ---------------- device scratch ----------------
__device__ __align__(16) __half d_E0h[Bv][Nn][256][NTT];   // exp(R0)*4096, [b][h][sc][a] fp16
__device__ __align__(16) __half d_E1h[Bv][Nn][256][NTT];
__device__ __align__(16) float d_U0t [Bv][Nn][Nn][NTT][NTT];  // [b][h][k][s][a]
__device__ __align__(16) float d_U1t [Bv][Nn][Nn][NTT][NTT];  // [b][h][k][c][a]
__device__ __align__(16) float d_V0t [Bv][Nn][TT][NTT];       // [b][h][c][a]
__device__ __align__(16) float d_V1t [Bv][Nn][TT][NTT];       // [b][h][s][a]
__device__ float d_beta [Bv][Nn+1][Nn+1][NTT][Nn];
__device__ float d_betau[Bv][Nn+1][Nn+1][NTT];
__device__ float d_Ssc  [Bv][Nn+1][Nn+1];

// ---------------- kernel 1: rule precompute + Ssc sentinel fill ----------------
__global__ void __launch_bounds__(256) k_pre(const float* __restrict__ rule,
                                             const float* __restrict__ unary) {
    int blk = blockIdx.x;
    int h = blk % Nn;
    int a = (blk / Nn) % NTT;
    int b = blk / (Nn * NTT);
    const float2* R2 = (const float2*)(rule + (size_t)((b * NTT + a) * Nn + h) * (TT * TT * 2));

    __shared__ float Er0[TT][65];   // padded: kills 16-way LDS conflict in U loops
    __shared__ float Er1[TT][65];
    __shared__ float eus[Nn][49];
    int tid = threadIdx.x;

    if (blk == 0) {  // sentinel-fill Ssc (doubles as dataflow flag); stream-ordered before k_chart
        for (int i = tid; i < Bv * (Nn + 1) * (Nn + 1); i += 256)
            ((unsigned*)&d_Ssc[0][0][0])[i] = SNAN;
    }

    for (int e = tid; e < TT * TT; e += 256) {
        float2 v = R2[e];
        int s = e >> 6, c = e & 63;
        Er0[s][c] = fexp(v.x);
        Er1[s][c] = fexp(v.y);
    }
    for (int t = tid; t < Nn * TSS; t += 256) {
        int k = t / TSS, c = t % TSS;
        eus[k][c] = fexp(unary[(b * Nn + k) * TT + NTT + c]);
    }
    __syncthreads();

    {
        int s = tid >> 4, c = tid & 15;
        d_E0h[b][h][s * 16 + c][a] = __float2half_rn(Er0[s][c] * ESCALE);
        d_E1h[b][h][s * 16 + c][a] = __float2half_rn(Er1[s][c] * ESCALE);
    }
    if (tid < 128) {
        int x = tid & 63;
        float acc = 0.f;
        if (tid < 64) {
            #pragma unroll 8
            for (int s = NTT; s < TT; s++) acc += Er0[s][x];
            d_V0t[b][h][x][a] = acc;
        } else {
            #pragma unroll 8
            for (int c = NTT; c < TT; c++) acc += Er1[x][c];
            d_V1t[b][h][x][a] = acc;
        }
    }
    if (tid < 192) {
        int which = tid / 96;
        int g = tid % 96;
        int x = g & 15, k0 = (g >> 4) * 4;
        float a0 = 0.f, a1 = 0.f, a2 = 0.f, a3 = 0.f;
        if (which == 0) {
            #pragma unroll 8
            for (int c = 0; c < TSS; c++) {
                float e = Er0[x][NTT + c];
                a0 += e * eus[k0 + 0][c];
                a1 += e * eus[k0 + 1][c];
                a2 += e * eus[k0 + 2][c];
                a3 += e * eus[k0 + 3][c];
            }
            d_U0t[b][h][k0 + 0][x][a] = a0;
            d_U0t[b][h][k0 + 1][x][a] = a1;
            d_U0t[b][h][k0 + 2][x][a] = a2;
            d_U0t[b][h][k0 + 3][x][a] = a3;
        } else {
            #pragma unroll 8
            for (int s = 0; s < TSS; s++) {
                float e = Er1[NTT + s][x];
                a0 += e * eus[k0 + 0][s];
                a1 += e * eus[k0 + 1][s];
                a2 += e * eus[k0 + 2][s];
                a3 += e * eus[k0 + 3][s];
            }
            d_U1t[b][h][k0 + 0][x][a] = a0;
            d_U1t[b][h][k0 + 1][x][a] = a1;
            d_U1t[b][h][k0 + 2][x][a] = a2;
            d_U1t[b][h][k0 + 3][x][a] = a3;
        }
    }
}

// spin until Ssc published (acquire semantics); integer compare = fast-math safe
__device__ __forceinline__ float spin_ssc(const float* p) {
    float v = ld_acquire_gpu(p);
    while (__float_as_uint(v) == SNAN) {
        __nanosleep(20);
        v = ld_acquire_gpu(p);
    }
    return v;
}

// ---------------- kernel 2: dataflow chart kernel ----------------
__global__ void __launch_bounds__(THR, 1) k_chart(const float* __restrict__ unary,
                                                  const float* __restrict__ root,
                                                  float* __restrict__ out) {
    extern __shared__ float dyn[];
    float* P0f  = dyn;                       // [24][264] fp32, row = hh, col = sc
    float* P1f  = dyn + 24 * 264;            // [24][264]
    float* ownB = dyn + 2 * 24 * 264;        // [23][16][24] fp32, slot = width-2
    __shared__ float eu_s[Nn][TT];
    __shared__ __align__(16) float wRTi[NTT][24][2];   // [c][jj]{w0, w1} interleaved
    __shared__ float BL2s[NTT][Nn];
    __shared__ float tmpsm[NTT][Nn];
    __shared__ float ownBu[Nn][NTT];   // slot = width-2
    __shared__ float ownS[Nn + 1];     // own Ssc by width
    __shared__ float wspe[Nn];
    __shared__ float buR0s[NTT];       // wspe[0]   * betau(l+1, r)
    __shared__ float buLW[NTT];        // wspe[W-2] * ownBu(l, r-1)
    __shared__ unsigned Msm_u;         // cell max as uint (tvals >= 0)
    __shared__ float sref_s;

    int tid = threadIdx.x;
    int b = blockIdx.x / NL;
    int l = blockIdx.x % NL;

    for (int t = tid; t < Nn * TT; t += THR)
        (&eu_s[0][0])[t] = fexp(unary[b * Nn * TT + t]);
    for (int t = tid; t < 8832; t += THR) ownB[t] = 0.f;
    if (tid < 2) ownS[tid] = 0.f;
    __syncthreads();

    int Wmax = Nn - l;
    for (int W = 2; W <= Wmax; W++) {
        int r = l + W;
        int nT = NTT * W;
        int a = tid & 15, hh = tid >> 4;

        if (tid == 32) Msm_u = 0u;   // reset cell max (ordered by the next sync)

        if (W >= 3) {
            // ---- phase 1: warp 0 spins on right children (acquire), computes weights ----
            if (tid < 32) {
                __syncwarp();   // order vs lane-0's ownS write last iteration
                int j = tid;
                float v = -1e30f;
                if (j <= W - 2) {
                    float sl = (j == 0)     ? 0.f : ownS[j + 1];
                    float sr = (j == W - 2) ? 0.f : spin_ssc(&d_Ssc[b][l + 1 + j][r]);
                    v = sl + sr;
                }
                float mx = v;
                #pragma unroll
                for (int o = 16; o > 0; o >>= 1) mx = fmaxf(mx, __shfl_xor_sync(0xffffffffu, mx, o));
                if (j <= W - 2) wspe[j] = expf(v - mx);
                if (j == 0) sref_s = mx;
            }
            __syncthreads();

            // ---- phase 2: interleaved weight tables + boundary child data ----
            {
                int c = tid / 24, jj = tid % 24;   // THR == 16*24
                int j = jj + 1;
                bool in = (j <= W - 3);
                wRTi[c][jj][0] = in ? wspe[j] * __ldcg(&d_betau[b][l + 1 + j][r][c]) : 0.f;
                wRTi[c][jj][1] = in ? wspe[j] * ownBu[j - 1][c] : 0.f;
            }
            if (tid < nT) {
                int c2 = tid / W, h2 = tid % W;
                BL2s[c2][h2] = __ldcg(&d_beta[b][l + 1][r][c2][l + h2]);
            }
            if (tid >= 352) {
                int c = tid - 352;
                if (c < NTT) {
                    buR0s[c] = wspe[0] * __ldcg(&d_betau[b][l + 1][r][c]);
                    buLW[c]  = wspe[W - 2] * ownBu[W - 3][c];
                }
            }
            __syncthreads();
        } else {
            if (tid == 0) sref_s = 0.f;
            __syncthreads();
        }

        if (W >= 4) {
            // ---- P build: both tables fused via FFMA2 ----
            if (tid < nT) {
                int phh = tid % W, x = tid / W;
                u64 bvp[24];
                #pragma unroll
                for (int j = 1; j <= 24; j++) {
                    if (j <= W - 3) {
                        float bl = ownB[(j - 1) * 384 + x * 24 + phh];
                        float br = __ldcg(&d_beta[b][l + 1 + j][r][x][l + phh]);
                        bvp[j - 1] = pack2(bl, br);
                    } else bvp[j - 1] = 0ULL;
                }
                #pragma unroll
                for (int c = 0; c < NTT; c++) {
                    u64 acc = 0ULL;
                    #pragma unroll
                    for (int k = 0; k < 6; k++) {
                        if (4 * k <= W - 4) {   // warp-uniform
                            const u64* wp = reinterpret_cast<const u64*>(&wRTi[c][4 * k][0]);
                            acc = ffma2(bvp[4 * k + 0], wp[0], acc);
                            acc = ffma2(bvp[4 * k + 1], wp[1], acc);
                            acc = ffma2(bvp[4 * k + 2], wp[2], acc);
                            acc = ffma2(bvp[4 * k + 3], wp[3], acc);
                        }
                    }
                    float2 pv = unpack2(acc);
                    P0f[phh * 264 + x * 16 + c] = pv.x;
                    P1f[phh * 264 + c * 16 + x] = pv.y;
                }
            }
            __syncthreads();

            // ---- contraction + folded boundary + per-warp max ----
            {
                int wd = tid >> 5, lane = tid & 31;
                int sc_lo = lane >> 1, a8 = lane & 1;
                float wspe0  = wspe[0];
                float wspeW2 = wspe[W - 2];
                float wmax = 0.f;
                for (int chh = wd; chh < W; chh += 12) {
                    const uint4* E0 = reinterpret_cast<const uint4*>(&d_E0h[b][l + chh][0][0]);
                    const uint4* E1 = reinterpret_cast<const uint4*>(&d_E1h[b][l + chh][0][0]);
                    const float* p0 = P0f + chh * 264;
                    const float* p1 = P1f + chh * 264;
                    float acc[8];
                    #pragma unroll
                    for (int k = 0; k < 8; k++) acc[k] = 0.f;
                    #pragma unroll
                    for (int i = 0; i < 16; i++) {
                        int sc = i * 16 + sc_lo;
                        float v0 = p0[sc];
                        float v1 = p1[sc];
                        uint4 e0 = __ldg(E0 + sc * 2 + a8);
                        uint4 e1 = __ldg(E1 + sc * 2 + a8);
                        float2 f;
                        f = __half22float2(*reinterpret_cast<const __half2*>(&e0.x));
                        acc[0] = fmaf(v0, f.x, acc[0]); acc[1] = fmaf(v0, f.y, acc[1]);
                        f = __half22float2(*reinterpret_cast<const __half2*>(&e0.y));
                        acc[2] = fmaf(v0, f.x, acc[2]); acc[3] = fmaf(v0, f.y, acc[3]);
                        f = __half22float2(*reinterpret_cast<const __half2*>(&e0.z));
                        acc[4] = fmaf(v0, f.x, acc[4]); acc[5] = fmaf(v0, f.y, acc[5]);
                        f = __half22float2(*reinterpret_cast<const __half2*>(&e0.w));
                        acc[6] = fmaf(v0, f.x, acc[6]); acc[7] = fmaf(v0, f.y, acc[7]);
                        f = __half22float2(*reinterpret_cast<const __half2*>(&e1.x));
                        acc[0] = fmaf(v1, f.x, acc[0]); acc[1] = fmaf(v1, f.y, acc[1]);
                        f = __half22float2(*reinterpret_cast<const __half2*>(&e1.y));
                        acc[2] = fmaf(v1, f.x, acc[2]); acc[3] = fmaf(v1, f.y, acc[3]);
                        f = __half22float2(*reinterpret_cast<const __half2*>(&e1.z));
                        acc[4] = fmaf(v1, f.x, acc[4]); acc[5] = fmaf(v1, f.y, acc[5]);
                        f = __half22float2(*reinterpret_cast<const __half2*>(&e1.w));
                        acc[6] = fmaf(v1, f.x, acc[6]); acc[7] = fmaf(v1, f.y, acc[7]);
                    }
                    // folded boundary terms (fp32 tables, weights pre-scaled by ESCALE)
                    {   // s2: U1(l+hh, k=l) . (wspe0 * BL2)
                        float v = wspe0 * ESCALE * BL2s[sc_lo][chh];
                        const float4* U1 = reinterpret_cast<const float4*>(
                            &d_U1t[b][l + chh][l][sc_lo][a8 * 8]);
                        float4 ua = __ldg(U1), ub = __ldg(U1 + 1);
                        acc[0] = fmaf(v, ua.x, acc[0]); acc[1] = fmaf(v, ua.y, acc[1]);
                        acc[2] = fmaf(v, ua.z, acc[2]); acc[3] = fmaf(v, ua.w, acc[3]);
                        acc[4] = fmaf(v, ub.x, acc[4]); acc[5] = fmaf(v, ub.y, acc[5]);
                        acc[6] = fmaf(v, ub.z, acc[6]); acc[7] = fmaf(v, ub.w, acc[7]);
                    }
                    {   // s3: U0(l+hh, k=r-1) . (wspeW2 * ownB(l, r-1))
                        float v = wspeW2 * ESCALE * ownB[(W - 3) * 384 + sc_lo * 24 + chh];
                        const float4* U0 = reinterpret_cast<const float4*>(
                            &d_U0t[b][l + chh][r - 1][sc_lo][a8 * 8]);
                        float4 ua = __ldg(U0), ub = __ldg(U0 + 1);
                        acc[0] = fmaf(v, ua.x, acc[0]); acc[1] = fmaf(v, ua.y, acc[1]);
                        acc[2] = fmaf(v, ua.z, acc[2]); acc[3] = fmaf(v, ua.w, acc[3]);
                        acc[4] = fmaf(v, ub.x, acc[4]); acc[5] = fmaf(v, ub.y, acc[5]);
                        acc[6] = fmaf(v, ub.z, acc[6]); acc[7] = fmaf(v, ub.w, acc[7]);
                    }
                    if (chh == 0) {   // s1: V0(l) . buR0s
                        float v = ESCALE * buR0s[sc_lo];
                        const float4* V0 = reinterpret_cast<const float4*>(
                            &d_V0t[b][l][sc_lo][a8 * 8]);
                        float4 ua = __ldg(V0), ub = __ldg(V0 + 1);
                        acc[0] = fmaf(v, ua.x, acc[0]); acc[1] = fmaf(v, ua.y, acc[1]);
                        acc[2] = fmaf(v, ua.z, acc[2]); acc[3] = fmaf(v, ua.w, acc[3]);
                        acc[4] = fmaf(v, ub.x, acc[4]); acc[5] = fmaf(v, ub.y, acc[5]);
                        acc[6] = fmaf(v, ub.z, acc[6]); acc[7] = fmaf(v, ub.w, acc[7]);
                    }
                    if (chh == W - 1) {   // s4: V1(r-1) . buLW
                        float v = ESCALE * buLW[sc_lo];
                        const float4* V1 = reinterpret_cast<const float4*>(
                            &d_V1t[b][r - 1][sc_lo][a8 * 8]);
                        float4 ua = __ldg(V1), ub = __ldg(V1 + 1);
                        acc[0] = fmaf(v, ua.x, acc[0]); acc[1] = fmaf(v, ua.y, acc[1]);
                        acc[2] = fmaf(v, ua.z, acc[2]); acc[3] = fmaf(v, ua.w, acc[3]);
                        acc[4] = fmaf(v, ub.x, acc[4]); acc[5] = fmaf(v, ub.y, acc[5]);
                        acc[6] = fmaf(v, ub.z, acc[6]); acc[7] = fmaf(v, ub.w, acc[7]);
                    }
                    #pragma unroll
                    for (int o = 2; o <= 16; o <<= 1) {
                        #pragma unroll
                        for (int k = 0; k < 8; k++)
                            acc[k] += __shfl_xor_sync(0xffffffffu, acc[k], o);
                    }
                    if (sc_lo == 0) {
                        int abase = a8 * 8;
                        #pragma unroll
                        for (int k = 0; k < 8; k++) {
                            float tv = acc[k] * EINV;
                            tmpsm[abase + k][chh] = tv;
                            wmax = fmaxf(wmax, tv);
                        }
                    }
                }
                // per-warp max -> one atomic
                wmax = fmaxf(wmax, __shfl_xor_sync(0xffffffffu, wmax, 1));
                if (lane == 0 && wmax > 0.f)
                    atomicMax(reinterpret_cast<int*>(const_cast<unsigned*>(&Msm_u)),
                              (int)__float_as_uint(wmax));
            }
            __syncthreads();
        } else {
            // ---- W == 2 / 3: small direct paths write tmpsm + per-warp max ----
            float tval = 0.f;
            if (tid < nT) {
                if (W == 3) {
                    float s2 = 0.f, s3 = 0.f;
                    #pragma unroll
                    for (int c = 0; c < NTT; c++) {
                        s2 += __ldg(&d_U1t[b][l + hh][l][c][a]) * BL2s[c][hh];
                        s3 += __ldg(&d_U0t[b][l + hh][r - 1][c][a]) * ownB[(W - 3) * 384 + c * 24 + hh];
                    }
                    tval = wspe[0] * s2 + wspe[W - 2] * s3;
                    if (hh == 0) {
                        float s1 = 0.f;
                        #pragma unroll
                        for (int c = 0; c < NTT; c++)
                            s1 += __ldg(&d_V0t[b][l][c][a]) * buR0s[c];
                        tval += s1;
                    }
                    if (hh == W - 1) {
                        float s4 = 0.f;
                        #pragma unroll
                        for (int c = 0; c < NTT; c++)
                            s4 += __ldg(&d_V1t[b][r - 1][c][a]) * buLW[c];
                        tval += s4;
                    }
                } else {  // W == 2
                    if (hh == 0) {
                        #pragma unroll 8
                        for (int c = 0; c < TSS; c++)
                            tval += eu_s[l + 1][NTT + c] * __ldg(&d_V0t[b][l][NTT + c][a]);
                    } else {
                        #pragma unroll 8
                        for (int c = 0; c < TSS; c++)
                            tval += eu_s[l][NTT + c] * __ldg(&d_V1t[b][l + 1][NTT + c][a]);
                    }
                }
                tmpsm[a][hh] = tval;
            }
            float wm = tval;
            #pragma unroll
            for (int o = 16; o > 0; o >>= 1) wm = fmaxf(wm, __shfl_xor_sync(0xffffffffu, wm, o));
            if ((tid & 31) == 0 && wm > 0.f)
                atomicMax(reinterpret_cast<int*>(const_cast<unsigned*>(&Msm_u)),
                          (int)__float_as_uint(wm));
            __syncthreads();
        }

        // ---- commit + publish (single release store = flag) ----
        float Msm = __uint_as_float(Msm_u);
        float invM = 1.f / Msm;
        {
            int ca = tid / Nn, habs = tid % Nn;   // THR == 16*24 exactly
            float v = 0.f;
            if (habs >= l && habs < r) {
                v = tmpsm[ca][habs - l] * invM;
                ownB[(W - 2) * 384 + ca * 24 + (habs - l)] = v;
            }
            __stcg(&d_beta[b][l][r][ca][habs], v);
        }
        if (tid < NTT) {
            float accu = 0.f;
            for (int h2 = 0; h2 < W; h2++)
                accu += tmpsm[tid][h2] * eu_s[l + h2][tid];
            float bu = accu * invM;
            __stcg(&d_betau[b][l][r][tid], bu);
            ownBu[W - 2][tid] = bu;
            if (W == Nn) {   // only block (b, 0): fused root reduction
                float v = bu * __expf(root[b * NTT + tid]);
                #pragma unroll
                for (int o = 8; o > 0; o >>= 1) v += __shfl_xor_sync(0xffffu, v, o);
                if (tid == 0) out[b] = sref_s + logf(Msm) + logf(v);
            }
        }
        __syncthreads();   // all stores done before the release store below
        if (tid == 0) {
            float ss = sref_s + logf(Msm);
            ownS[W] = ss;
            st_release_gpu(&d_Ssc[b][l][r], ss);   // cumulative release publishes all stores
        }
        // no trailing sync: Msm_u reset (tid 32) is ordered by the next phase-1 barrier,
        // and ownS read (warp 0) is ordered by its __syncwarp.
    }
}

// ---------------- launch ----------------
extern "C" void kernel_launch(void* const* d_in, const int* in_sizes, int n_in,
                              void* d_out, int out_size) {
    const float* unary = nullptr;
    const float* rule  = nullptr;
    const float* root  = nullptr;
    for (int i = 0; i < n_in; i++) {
        if (in_sizes[i] == Bv * Nn * TT)                      unary = (const float*)d_in[i];
        else if (in_sizes[i] == Bv * NTT * Nn * TT * TT * 2)  rule  = (const float*)d_in[i];
        else if (in_sizes[i] == Bv * NTT)                     root  = (const float*)d_in[i];
    }

    int dynBytes = (2 * 24 * 264 + 23 * 16 * 24) * (int)sizeof(float);  // 86016
    cudaFuncSetAttribute(k_chart, cudaFuncAttributeMaxDynamicSharedMemorySize, dynBytes);

    k_pre<<<Bv * NTT * Nn, 256>>>(rule, unary);
    k_chart<<<Bv * NL, THR, dynBytes>>>(unary, root, (float*)d_out);
}

// round 14
// speedup vs baseline: 1.2320x; 1.0237x over previous
#include <cuda_runtime.h>
#include <cuda_fp16.h>
#include <math.h>

#define Bv  4
#define Nn  24
#define NTT 16
#define TSS 48
#define TT  64
#define THR 384
#define NL  (Nn - 1)          // 23 l-slots per batch
#define SNAN 0x7fc00000u      // Ssc "not ready" sentinel
#define ESCALE 4096.0f
#define EINV   (1.0f / 4096.0f)

typedef unsigned long long u64;

// ---- packed fp32x2 helpers (sm_103a) ----
__device__ __forceinline__ u64 ffma2(u64 a, u64 b, u64 c) {
    u64 d;
    asm("fma.rn.f32x2 %0, %1, %2, %3;" : "=l"(d) : "l"(a), "l"(b), "l"(c));
    return d;
}
__device__ __forceinline__ u64 pack2(float x, float y) {
    u64 d;
    asm("mov.b64 %0, {%1, %2};" : "=l"(d) : "f"(x), "f"(y));
    return d;
}
__device__ __forceinline__ float2 unpack2(u64 v) {
    float2 f;
    asm("mov.b64 {%0, %1}, %2;" : "=f"(f.x), "=f"(f.y) : "l"(v));
    return f;
}

// ---- fast exp: magic-number round + deg-5 Taylor (rel err ~2.4e-6) ----
__device__ __forceinline__ float fexp(float x) {
    x = fmaxf(x, -80.f);
    float k  = fmaf(x, 1.4426950408889634f, 12582912.f);
    int   n  = __float_as_int(k) - 0x4B400000;
    float nf = k - 12582912.f;
    float f  = fmaf(x, 1.4426950408889634f, -nf);
    float p  = 0.0013333558f;
    p = fmaf(p, f, 0.0096181291f);
    p = fmaf(p, f, 0.0555041086f);
    p = fmaf(p, f, 0.2402265069f);
    p = fmaf(p, f, 0.6931471806f);
    p = fmaf(p, f, 1.0f);
    return p * __int_as_float((n + 127) << 23);
}

// ---- release/acquire publish primitives (GPU scope, cumulative) ----
__device__ __forceinline__ void st_release_gpu(float* p, float v) {
    asm volatile("st.release.gpu.global.b32 [%0], %1;" :: "l"(p), "f"(v) : "memory");
}
__device__ __forceinline__ float ld_acquire_gpu(const float* p) {
    float v;
    asm volatile("ld.acquire.gpu.global.b32 %0, [%1];" : "=f"(v) : "l"(p) : "memory");
    return v;
}

// ---------------- device scratch ----------------
__device__ __align__(16) __half d_E0h[Bv][Nn][256][NTT];   // exp(R0)*4096, [b][h][sc][a] fp16
__device__ __align__(16) __half d_E1h[Bv][Nn][256][NTT];
__device__ __align__(16) float d_U0t [Bv][Nn][Nn][NTT][NTT];  // [b][h][k][s][a]
__device__ __align__(16) float d_U1t [Bv][Nn][Nn][NTT][NTT];  // [b][h][k][c][a]
__device__ __align__(16) float d_V0t [Bv][Nn][TT][NTT];       // [b][h][c][a]
__device__ __align__(16) float d_V1t [Bv][Nn][TT][NTT];       // [b][h][s][a]
__device__ float d_beta [Bv][Nn+1][Nn+1][NTT][Nn];
__device__ float d_betau[Bv][Nn+1][Nn+1][NTT];
__device__ float d_Ssc  [Bv][Nn+1][Nn+1];

// ---------------- kernel 1: rule precompute + Ssc sentinel fill ----------------
__global__ void __launch_bounds__(256) k_pre(const float* __restrict__ rule,
                                             const float* __restrict__ unary) {
    int blk = blockIdx.x;
    int h = blk % Nn;
    int a = (blk / Nn) % NTT;
    int b = blk / (Nn * NTT);
    const float4* R4 = (const float4*)(rule + (size_t)((b * NTT + a) * Nn + h) * (TT * TT * 2));

    __shared__ float Er0[TT][65];   // padded: kills 16-way LDS conflict in U loops
    __shared__ float Er1[TT][65];
    __shared__ float eus[Nn][49];
    int tid = threadIdx.x;

    if (blk == 0) {  // sentinel-fill Ssc (doubles as dataflow flag); stream-ordered before k_chart
        for (int i = tid; i < Bv * (Nn + 1) * (Nn + 1); i += 256)
            ((unsigned*)&d_Ssc[0][0][0])[i] = SNAN;
    }

    // float4 = {R0[i], R1[i], R0[i+1], R1[i+1]} for even i
    #pragma unroll 4
    for (int e = tid; e < TT * TT / 2; e += 256) {
        float4 v = R4[e];
        int i = e * 2;
        int s = i >> 6, c = i & 63;
        Er0[s][c]     = fexp(v.x);
        Er1[s][c]     = fexp(v.y);
        Er0[s][c + 1] = fexp(v.z);
        Er1[s][c + 1] = fexp(v.w);
    }
    for (int t = tid; t < Nn * TSS; t += 256) {
        int k = t / TSS, c = t % TSS;
        eus[k][c] = fexp(unary[(b * Nn + k) * TT + NTT + c]);
    }
    __syncthreads();

    {
        int s = tid >> 4, c = tid & 15;
        d_E0h[b][h][s * 16 + c][a] = __float2half_rn(Er0[s][c] * ESCALE);
        d_E1h[b][h][s * 16 + c][a] = __float2half_rn(Er1[s][c] * ESCALE);
    }
    if (tid < 128) {
        int x = tid & 63;
        float acc = 0.f;
        if (tid < 64) {
            #pragma unroll 8
            for (int s = NTT; s < TT; s++) acc += Er0[s][x];
            d_V0t[b][h][x][a] = acc;
        } else {
            #pragma unroll 8
            for (int c = NTT; c < TT; c++) acc += Er1[x][c];
            d_V1t[b][h][x][a] = acc;
        }
    }
    if (tid < 192) {
        int which = tid / 96;
        int g = tid % 96;
        int x = g & 15, k0 = (g >> 4) * 4;
        float a0 = 0.f, a1 = 0.f, a2 = 0.f, a3 = 0.f;
        if (which == 0) {
            #pragma unroll 8
            for (int c = 0; c < TSS; c++) {
                float e = Er0[x][NTT + c];
                a0 += e * eus[k0 + 0][c];
                a1 += e * eus[k0 + 1][c];
                a2 += e * eus[k0 + 2][c];
                a3 += e * eus[k0 + 3][c];
            }
            d_U0t[b][h][k0 + 0][x][a] = a0;
            d_U0t[b][h][k0 + 1][x][a] = a1;
            d_U0t[b][h][k0 + 2][x][a] = a2;
            d_U0t[b][h][k0 + 3][x][a] = a3;
        } else {
            #pragma unroll 8
            for (int s = 0; s < TSS; s++) {
                float e = Er1[NTT + s][x];
                a0 += e * eus[k0 + 0][s];
                a1 += e * eus[k0 + 1][s];
                a2 += e * eus[k0 + 2][s];
                a3 += e * eus[k0 + 3][s];
            }
            d_U1t[b][h][k0 + 0][x][a] = a0;
            d_U1t[b][h][k0 + 1][x][a] = a1;
            d_U1t[b][h][k0 + 2][x][a] = a2;
            d_U1t[b][h][k0 + 3][x][a] = a3;
        }
    }
}

// spin until Ssc published (acquire semantics); integer compare = fast-math safe
__device__ __forceinline__ float spin_ssc(const float* p) {
    float v = ld_acquire_gpu(p);
    while (__float_as_uint(v) == SNAN) {
        __nanosleep(20);
        v = ld_acquire_gpu(p);
    }
    return v;
}

// per-warp spin + split-weight computation; returns this lane's wspe value,
// writes sref_s (lane 0 of warp 0 / thread tid==0). Ends with a warp fence so
// every lane's subsequent loads are ordered after all lanes' acquires.
__device__ __forceinline__ float warp_wspe(int W, int b, int l, int r,
                                           const float* ownS, float* sref_s,
                                           int tid) {
    int j = tid & 31;
    float v = -1e30f;
    if (j <= W - 2) {
        float sl = (j == 0)     ? 0.f : ownS[j + 1];
        float sr = (j == W - 2) ? 0.f : spin_ssc(&d_Ssc[b][l + 1 + j][r]);
        v = sl + sr;
    }
    float mx = v;
    #pragma unroll
    for (int o = 16; o > 0; o >>= 1) mx = fmaxf(mx, __shfl_xor_sync(0xffffffffu, mx, o));
    float w = (j <= W - 2) ? expf(v - mx) : 0.f;
    if (tid == 0) *sref_s = mx;
    __syncwarp();   // warp-level memory fence: propagate all lanes' acquires
    return w;
}

// ---------------- kernel 2: dataflow chart kernel ----------------
__global__ void __launch_bounds__(THR, 1) k_chart(const float* __restrict__ unary,
                                                  const float* __restrict__ root,
                                                  float* __restrict__ out) {
    extern __shared__ float dyn[];
    float* P0f  = dyn;                       // [24][264] fp32, row = hh, col = sc
    float* P1f  = dyn + 24 * 264;            // [24][264]
    float* ownB = dyn + 2 * 24 * 264;        // [23][16][24] fp32, slot = width-2
    __shared__ float eu_s[Nn][TT];
    __shared__ __align__(16) float wRTi[NTT][24][2];   // [c][jj]{w0, w1} interleaved
    __shared__ float BL2s[NTT][Nn];
    __shared__ float tmpsm[NTT][Nn];
    __shared__ float ownBu[Nn][NTT];   // slot = width-2
    __shared__ float ownS[Nn + 1];     // own Ssc by width
    __shared__ float buR0s[NTT];       // wspe[0]   * betau(l+1, r)
    __shared__ float buLW[NTT];        // wspe[W-2] * ownBu(l, r-1)
    __shared__ unsigned Msm_u;         // cell max as uint (tvals >= 0)
    __shared__ float sref_s;

    int tid = threadIdx.x;
    int b = blockIdx.x / NL;
    int l = blockIdx.x % NL;

    for (int t = tid; t < Nn * TT; t += THR)
        (&eu_s[0][0])[t] = fexp(unary[b * Nn * TT + t]);
    for (int t = tid; t < 8832; t += THR) ownB[t] = 0.f;
    if (tid < 2) ownS[tid] = 0.f;
    if (tid == 32) Msm_u = 0u;
    __syncthreads();

    int Wmax = Nn - l;
    for (int W = 2; W <= Wmax; W++) {
        int r = l + W;
        int nT = NTT * W;
        int a = tid & 15, hh = tid >> 4;
        float wl = 0.f;   // this lane's wspe value (per-warp redundant)

        if (W >= 4) {
            // ======== phase A (no block barrier before it) ========
            wl = warp_wspe(W, b, l, r, ownS, &sref_s, tid);

            // weight tables + boundary child data (uses own-warp wspe via shfl)
            {
                int c = tid / 24, jj = tid % 24;   // THR == 16*24
                int j = jj + 1;
                bool in = (j <= W - 3);
                float wj = __shfl_sync(0xffffffffu, wl, j & 31);
                wRTi[c][jj][0] = in ? wj * __ldcg(&d_betau[b][l + 1 + j][r][c]) : 0.f;
                wRTi[c][jj][1] = in ? wj * ownBu[j - 1][c] : 0.f;
            }
            if (tid < nT) {
                int c2 = tid / W, h2 = tid % W;
                BL2s[c2][h2] = __ldcg(&d_beta[b][l + 1][r][c2][l + h2]);
            }
            if (tid >= 352) {
                float w0  = __shfl_sync(0xffffffffu, wl, 0);
                float wW2 = __shfl_sync(0xffffffffu, wl, W - 2);
                int c = tid - 352;
                if (c < NTT) {
                    buR0s[c] = w0  * __ldcg(&d_betau[b][l + 1][r][c]);
                    buLW[c]  = wW2 * ownBu[W - 3][c];
                }
            }

            // hoisted P-build child loads (need only the acquire, done per-warp)
            u64 bvp[24];
            int phh = tid % W, x = tid / W;
            if (tid < nT) {
                #pragma unroll
                for (int j = 1; j <= 24; j++) {
                    if (j <= W - 3) {
                        float bl = ownB[(j - 1) * 384 + x * 24 + phh];
                        float br = __ldcg(&d_beta[b][l + 1 + j][r][x][l + phh]);
                        bvp[j - 1] = pack2(bl, br);
                    } else bvp[j - 1] = 0ULL;
                }
            }
            __syncthreads();   // bar 1

            // ======== P-build FMA: both tables fused via FFMA2 ========
            if (tid < nT) {
                #pragma unroll
                for (int c = 0; c < NTT; c++) {
                    u64 acc = 0ULL;
                    #pragma unroll
                    for (int k = 0; k < 6; k++) {
                        if (4 * k <= W - 4) {   // warp-uniform
                            const u64* wp = reinterpret_cast<const u64*>(&wRTi[c][4 * k][0]);
                            acc = ffma2(bvp[4 * k + 0], wp[0], acc);
                            acc = ffma2(bvp[4 * k + 1], wp[1], acc);
                            acc = ffma2(bvp[4 * k + 2], wp[2], acc);
                            acc = ffma2(bvp[4 * k + 3], wp[3], acc);
                        }
                    }
                    float2 pv = unpack2(acc);
                    P0f[phh * 264 + x * 16 + c] = pv.x;
                    P1f[phh * 264 + c * 16 + x] = pv.y;
                }
            }
            __syncthreads();   // bar 2

            // ======== contraction + folded boundary + per-warp max ========
            {
                int wd = tid >> 5, lane = tid & 31;
                int sc_lo = lane >> 1, a8 = lane & 1;
                float wspe0  = __shfl_sync(0xffffffffu, wl, 0);
                float wspeW2 = __shfl_sync(0xffffffffu, wl, W - 2);
                float wmax = 0.f;
                for (int chh = wd; chh < W; chh += 12) {
                    const uint4* E0 = reinterpret_cast<const uint4*>(&d_E0h[b][l + chh][0][0]);
                    const uint4* E1 = reinterpret_cast<const uint4*>(&d_E1h[b][l + chh][0][0]);
                    const float* p0 = P0f + chh * 264;
                    const float* p1 = P1f + chh * 264;
                    float acc[8];
                    #pragma unroll
                    for (int k = 0; k < 8; k++) acc[k] = 0.f;
                    #pragma unroll
                    for (int i = 0; i < 16; i++) {
                        int sc = i * 16 + sc_lo;
                        float v0 = p0[sc];
                        float v1 = p1[sc];
                        uint4 e0 = __ldg(E0 + sc * 2 + a8);
                        uint4 e1 = __ldg(E1 + sc * 2 + a8);
                        float2 f;
                        f = __half22float2(*reinterpret_cast<const __half2*>(&e0.x));
                        acc[0] = fmaf(v0, f.x, acc[0]); acc[1] = fmaf(v0, f.y, acc[1]);
                        f = __half22float2(*reinterpret_cast<const __half2*>(&e0.y));
                        acc[2] = fmaf(v0, f.x, acc[2]); acc[3] = fmaf(v0, f.y, acc[3]);
                        f = __half22float2(*reinterpret_cast<const __half2*>(&e0.z));
                        acc[4] = fmaf(v0, f.x, acc[4]); acc[5] = fmaf(v0, f.y, acc[5]);
                        f = __half22float2(*reinterpret_cast<const __half2*>(&e0.w));
                        acc[6] = fmaf(v0, f.x, acc[6]); acc[7] = fmaf(v0, f.y, acc[7]);
                        f = __half22float2(*reinterpret_cast<const __half2*>(&e1.x));
                        acc[0] = fmaf(v1, f.x, acc[0]); acc[1] = fmaf(v1, f.y, acc[1]);
                        f = __half22float2(*reinterpret_cast<const __half2*>(&e1.y));
                        acc[2] = fmaf(v1, f.x, acc[2]); acc[3] = fmaf(v1, f.y, acc[3]);
                        f = __half22float2(*reinterpret_cast<const __half2*>(&e1.z));
                        acc[4] = fmaf(v1, f.x, acc[4]); acc[5] = fmaf(v1, f.y, acc[5]);
                        f = __half22float2(*reinterpret_cast<const __half2*>(&e1.w));
                        acc[6] = fmaf(v1, f.x, acc[6]); acc[7] = fmaf(v1, f.y, acc[7]);
                    }
                    // folded boundary terms (fp32 tables, weights pre-scaled by ESCALE)
                    {   // s2: U1(l+hh, k=l) . (wspe0 * BL2)
                        float v = wspe0 * ESCALE * BL2s[sc_lo][chh];
                        const float4* U1 = reinterpret_cast<const float4*>(
                            &d_U1t[b][l + chh][l][sc_lo][a8 * 8]);
                        float4 ua = __ldg(U1), ub = __ldg(U1 + 1);
                        acc[0] = fmaf(v, ua.x, acc[0]); acc[1] = fmaf(v, ua.y, acc[1]);
                        acc[2] = fmaf(v, ua.z, acc[2]); acc[3] = fmaf(v, ua.w, acc[3]);
                        acc[4] = fmaf(v, ub.x, acc[4]); acc[5] = fmaf(v, ub.y, acc[5]);
                        acc[6] = fmaf(v, ub.z, acc[6]); acc[7] = fmaf(v, ub.w, acc[7]);
                    }
                    {   // s3: U0(l+hh, k=r-1) . (wspeW2 * ownB(l, r-1))
                        float v = wspeW2 * ESCALE * ownB[(W - 3) * 384 + sc_lo * 24 + chh];
                        const float4* U0 = reinterpret_cast<const float4*>(
                            &d_U0t[b][l + chh][r - 1][sc_lo][a8 * 8]);
                        float4 ua = __ldg(U0), ub = __ldg(U0 + 1);
                        acc[0] = fmaf(v, ua.x, acc[0]); acc[1] = fmaf(v, ua.y, acc[1]);
                        acc[2] = fmaf(v, ua.z, acc[2]); acc[3] = fmaf(v, ua.w, acc[3]);
                        acc[4] = fmaf(v, ub.x, acc[4]); acc[5] = fmaf(v, ub.y, acc[5]);
                        acc[6] = fmaf(v, ub.z, acc[6]); acc[7] = fmaf(v, ub.w, acc[7]);
                    }
                    if (chh == 0) {   // s1: V0(l) . buR0s
                        float v = ESCALE * buR0s[sc_lo];
                        const float4* V0 = reinterpret_cast<const float4*>(
                            &d_V0t[b][l][sc_lo][a8 * 8]);
                        float4 ua = __ldg(V0), ub = __ldg(V0 + 1);
                        acc[0] = fmaf(v, ua.x, acc[0]); acc[1] = fmaf(v, ua.y, acc[1]);
                        acc[2] = fmaf(v, ua.z, acc[2]); acc[3] = fmaf(v, ua.w, acc[3]);
                        acc[4] = fmaf(v, ub.x, acc[4]); acc[5] = fmaf(v, ub.y, acc[5]);
                        acc[6] = fmaf(v, ub.z, acc[6]); acc[7] = fmaf(v, ub.w, acc[7]);
                    }
                    if (chh == W - 1) {   // s4: V1(r-1) . buLW
                        float v = ESCALE * buLW[sc_lo];
                        const float4* V1 = reinterpret_cast<const float4*>(
                            &d_V1t[b][r - 1][sc_lo][a8 * 8]);
                        float4 ua = __ldg(V1), ub = __ldg(V1 + 1);
                        acc[0] = fmaf(v, ua.x, acc[0]); acc[1] = fmaf(v, ua.y, acc[1]);
                        acc[2] = fmaf(v, ua.z, acc[2]); acc[3] = fmaf(v, ua.w, acc[3]);
                        acc[4] = fmaf(v, ub.x, acc[4]); acc[5] = fmaf(v, ub.y, acc[5]);
                        acc[6] = fmaf(v, ub.z, acc[6]); acc[7] = fmaf(v, ub.w, acc[7]);
                    }
                    #pragma unroll
                    for (int o = 2; o <= 16; o <<= 1) {
                        #pragma unroll
                        for (int k = 0; k < 8; k++)
                            acc[k] += __shfl_xor_sync(0xffffffffu, acc[k], o);
                    }
                    if (sc_lo == 0) {
                        int abase = a8 * 8;
                        #pragma unroll
                        for (int k = 0; k < 8; k++) {
                            float tv = acc[k] * EINV;
                            tmpsm[abase + k][chh] = tv;
                            wmax = fmaxf(wmax, tv);
                        }
                    }
                }
                wmax = fmaxf(wmax, __shfl_xor_sync(0xffffffffu, wmax, 1));
                if (lane == 0 && wmax > 0.f)
                    atomicMax(reinterpret_cast<int*>(const_cast<unsigned*>(&Msm_u)),
                              (int)__float_as_uint(wmax));
            }
            __syncthreads();   // bar 3
        } else {
            // ======== W == 2 / 3 ========
            float w0 = 1.f, wW2 = 1.f;
            if (W == 3) {
                wl = warp_wspe(W, b, l, r, ownS, &sref_s, tid);
                w0  = __shfl_sync(0xffffffffu, wl, 0);
                wW2 = __shfl_sync(0xffffffffu, wl, W - 2);
                if (tid < nT) {
                    int c2 = tid / W, h2 = tid % W;
                    BL2s[c2][h2] = __ldcg(&d_beta[b][l + 1][r][c2][l + h2]);
                }
                if (tid >= 352) {
                    int c = tid - 352;
                    if (c < NTT) {
                        buR0s[c] = w0  * __ldcg(&d_betau[b][l + 1][r][c]);
                        buLW[c]  = wW2 * ownBu[W - 3][c];
                    }
                }
            } else {
                if (tid == 0) sref_s = 0.f;
            }
            __syncthreads();   // bar 1

            float tval = 0.f;
            if (tid < nT) {
                if (W == 3) {
                    float s2 = 0.f, s3 = 0.f;
                    #pragma unroll
                    for (int c = 0; c < NTT; c++) {
                        s2 += __ldg(&d_U1t[b][l + hh][l][c][a]) * BL2s[c][hh];
                        s3 += __ldg(&d_U0t[b][l + hh][r - 1][c][a]) * ownB[0 * 384 + c * 24 + hh];
                    }
                    tval = w0 * s2 + wW2 * s3;
                    if (hh == 0) {
                        float s1 = 0.f;
                        #pragma unroll
                        for (int c = 0; c < NTT; c++)
                            s1 += __ldg(&d_V0t[b][l][c][a]) * buR0s[c];
                        tval += s1;
                    }
                    if (hh == W - 1) {
                        float s4 = 0.f;
                        #pragma unroll
                        for (int c = 0; c < NTT; c++)
                            s4 += __ldg(&d_V1t[b][r - 1][c][a]) * buLW[c];
                        tval += s4;
                    }
                } else {  // W == 2
                    if (hh == 0) {
                        #pragma unroll 8
                        for (int c = 0; c < TSS; c++)
                            tval += eu_s[l + 1][NTT + c] * __ldg(&d_V0t[b][l][NTT + c][a]);
                    } else {
                        #pragma unroll 8
                        for (int c = 0; c < TSS; c++)
                            tval += eu_s[l][NTT + c] * __ldg(&d_V1t[b][l + 1][NTT + c][a]);
                    }
                }
                tmpsm[a][hh] = tval;
            }
            float wm = tval;
            #pragma unroll
            for (int o = 16; o > 0; o >>= 1) wm = fmaxf(wm, __shfl_xor_sync(0xffffffffu, wm, o));
            if ((tid & 31) == 0 && wm > 0.f)
                atomicMax(reinterpret_cast<int*>(const_cast<unsigned*>(&Msm_u)),
                          (int)__float_as_uint(wm));
            __syncthreads();   // bar 3
        }

        // ======== commit + publish ========
        float Msm = __uint_as_float(Msm_u);
        float invM = 1.f / Msm;
        {
            int ca = tid / Nn, habs = tid % Nn;   // THR == 16*24 exactly
            float v = 0.f;
            if (habs >= l && habs < r) {
                v = tmpsm[ca][habs - l] * invM;
                ownB[(W - 2) * 384 + ca * 24 + (habs - l)] = v;
            }
            __stcg(&d_beta[b][l][r][ca][habs], v);
        }
        if (tid < NTT) {
            float accu = 0.f;
            for (int h2 = 0; h2 < W; h2++)
                accu += tmpsm[tid][h2] * eu_s[l + h2][tid];
            float bu = accu * invM;
            __stcg(&d_betau[b][l][r][tid], bu);
            ownBu[W - 2][tid] = bu;
            if (W == Nn) {   // only block (b, 0): fused root reduction
                float v = bu * __expf(root[b * NTT + tid]);
                #pragma unroll
                for (int o = 8; o > 0; o >>= 1) v += __shfl_xor_sync(0xffffu, v, o);
                if (tid == 0) out[b] = sref_s + logf(Msm) + logf(v);
            }
        }
        float ss = 0.f;
        if (tid == 0) {
            ss = sref_s + logf(Msm);
            ownS[W] = ss;   // written BEFORE bar 4 so all warps may read it next cell
        }
        __syncthreads();   // bar 4: all stores + ownS ordered before release
        if (tid == 0) st_release_gpu(&d_Ssc[b][l][r], ss);
        if (tid == 32) Msm_u = 0u;   // ordered for consumers by next cell's bar 1/2
    }
}

// ---------------- launch ----------------
extern "C" void kernel_launch(void* const* d_in, const int* in_sizes, int n_in,
                              void* d_out, int out_size) {
    const float* unary = nullptr;
    const float* rule  = nullptr;
    const float* root  = nullptr;
    for (int i = 0; i < n_in; i++) {
        if (in_sizes[i] == Bv * Nn * TT)                      unary = (const float*)d_in[i];
        else if (in_sizes[i] == Bv * NTT * Nn * TT * TT * 2)  rule  = (const float*)d_in[i];
        else if (in_sizes[i] == Bv * NTT)                     root  = (const float*)d_in[i];
    }

    int dynBytes = (2 * 24 * 264 + 23 * 16 * 24) * (int)sizeof(float);  // 86016
    cudaFuncSetAttribute(k_chart, cudaFuncAttributeMaxDynamicSharedMemorySize, dynBytes);

    k_pre<<<Bv * NTT * Nn, 256>>>(rule, unary);
    k_chart<<<Bv * NL, THR, dynBytes>>>(unary, root, (float*)d_out);
}

// round 15
// speedup vs baseline: 1.2473x; 1.0124x over previous
#include <cuda_runtime.h>
#include <cuda_fp16.h>
#include <math.h>

#define Bv  4
#define Nn  24
#define NTT 16
#define TSS 48
#define TT  64
#define THR 384
#define NL  (Nn - 1)          // 23 l-slots per batch
#define SNAN 0x7fc00000u      // Ssc "not ready" sentinel
#define ESCALE 4096.0f
#define EINV   (1.0f / 4096.0f)

typedef unsigned long long u64;

// ---- packed fp32x2 helpers (sm_103a) ----
__device__ __forceinline__ u64 ffma2(u64 a, u64 b, u64 c) {
    u64 d;
    asm("fma.rn.f32x2 %0, %1, %2, %3;" : "=l"(d) : "l"(a), "l"(b), "l"(c));
    return d;
}
__device__ __forceinline__ u64 pack2(float x, float y) {
    u64 d;
    asm("mov.b64 %0, {%1, %2};" : "=l"(d) : "f"(x), "f"(y));
    return d;
}
__device__ __forceinline__ float2 unpack2(u64 v) {
    float2 f;
    asm("mov.b64 {%0, %1}, %2;" : "=f"(f.x), "=f"(f.y) : "l"(v));
    return f;
}

// ---- fast exp: magic-number round + deg-5 Taylor (rel err ~2.4e-6) ----
__device__ __forceinline__ float fexp(float x) {
    x = fmaxf(x, -80.f);
    float k  = fmaf(x, 1.4426950408889634f, 12582912.f);
    int   n  = __float_as_int(k) - 0x4B400000;
    float nf = k - 12582912.f;
    float f  = fmaf(x, 1.4426950408889634f, -nf);
    float p  = 0.0013333558f;
    p = fmaf(p, f, 0.0096181291f);
    p = fmaf(p, f, 0.0555041086f);
    p = fmaf(p, f, 0.2402265069f);
    p = fmaf(p, f, 0.6931471806f);
    p = fmaf(p, f, 1.0f);
    return p * __int_as_float((n + 127) << 23);
}

// ---- release/acquire publish primitives (GPU scope, cumulative) ----
__device__ __forceinline__ void st_release_gpu(float* p, float v) {
    asm volatile("st.release.gpu.global.b32 [%0], %1;" :: "l"(p), "f"(v) : "memory");
}
__device__ __forceinline__ float ld_acquire_gpu(const float* p) {
    float v;
    asm volatile("ld.acquire.gpu.global.b32 %0, [%1];" : "=f"(v) : "l"(p) : "memory");
    return v;
}

// ---------------- device scratch ----------------
__device__ __align__(16) __half d_E0h[Bv][Nn][256][NTT];   // exp(R0)*4096, [b][h][sc][a] fp16
__device__ __align__(16) __half d_E1h[Bv][Nn][256][NTT];
__device__ __align__(16) float d_U0t [Bv][Nn][Nn][NTT][NTT];  // [b][h][k][s][a]
__device__ __align__(16) float d_U1t [Bv][Nn][Nn][NTT][NTT];  // [b][h][k][c][a]
__device__ __align__(16) float d_V0t [Bv][Nn][TT][NTT];       // [b][h][c][a]
__device__ __align__(16) float d_V1t [Bv][Nn][TT][NTT];       // [b][h][s][a]
__device__ float d_beta [Bv][Nn+1][Nn+1][NTT][Nn];
__device__ float d_betau[Bv][Nn+1][Nn+1][NTT];
__device__ float d_Ssc  [Bv][Nn+1][Nn+1];

// ---------------- kernel 1: rule precompute + Ssc sentinel fill ----------------
__global__ void __launch_bounds__(256) k_pre(const float* __restrict__ rule,
                                             const float* __restrict__ unary) {
    int blk = blockIdx.x;
    int h = blk % Nn;
    int a = (blk / Nn) % NTT;
    int b = blk / (Nn * NTT);
    const float4* R4 = (const float4*)(rule + (size_t)((b * NTT + a) * Nn + h) * (TT * TT * 2));

    __shared__ float Er0[TT][65];   // padded: kills 16-way LDS conflict in U loops
    __shared__ float Er1[TT][65];
    __shared__ float eus[Nn][49];
    int tid = threadIdx.x;

    if (blk == 0) {  // sentinel-fill Ssc (doubles as dataflow flag); stream-ordered before k_chart
        for (int i = tid; i < Bv * (Nn + 1) * (Nn + 1); i += 256)
            ((unsigned*)&d_Ssc[0][0][0])[i] = SNAN;
    }

    // float4 = {R0[i], R1[i], R0[i+1], R1[i+1]} for even i
    #pragma unroll 4
    for (int e = tid; e < TT * TT / 2; e += 256) {
        float4 v = R4[e];
        int i = e * 2;
        int s = i >> 6, c = i & 63;
        Er0[s][c]     = fexp(v.x);
        Er1[s][c]     = fexp(v.y);
        Er0[s][c + 1] = fexp(v.z);
        Er1[s][c + 1] = fexp(v.w);
    }
    for (int t = tid; t < Nn * TSS; t += 256) {
        int k = t / TSS, c = t % TSS;
        eus[k][c] = fexp(unary[(b * Nn + k) * TT + NTT + c]);
    }
    __syncthreads();

    {
        int s = tid >> 4, c = tid & 15;
        d_E0h[b][h][s * 16 + c][a] = __float2half_rn(Er0[s][c] * ESCALE);
        d_E1h[b][h][s * 16 + c][a] = __float2half_rn(Er1[s][c] * ESCALE);
    }
    if (tid < 128) {
        int x = tid & 63;
        float acc = 0.f;
        if (tid < 64) {
            #pragma unroll 8
            for (int s = NTT; s < TT; s++) acc += Er0[s][x];
            d_V0t[b][h][x][a] = acc;
        } else {
            #pragma unroll 8
            for (int c = NTT; c < TT; c++) acc += Er1[x][c];
            d_V1t[b][h][x][a] = acc;
        }
    }
    if (tid < 192) {
        int which = tid / 96;
        int g = tid % 96;
        int x = g & 15, k0 = (g >> 4) * 4;
        float a0 = 0.f, a1 = 0.f, a2 = 0.f, a3 = 0.f;
        if (which == 0) {
            #pragma unroll 8
            for (int c = 0; c < TSS; c++) {
                float e = Er0[x][NTT + c];
                a0 += e * eus[k0 + 0][c];
                a1 += e * eus[k0 + 1][c];
                a2 += e * eus[k0 + 2][c];
                a3 += e * eus[k0 + 3][c];
            }
            d_U0t[b][h][k0 + 0][x][a] = a0;
            d_U0t[b][h][k0 + 1][x][a] = a1;
            d_U0t[b][h][k0 + 2][x][a] = a2;
            d_U0t[b][h][k0 + 3][x][a] = a3;
        } else {
            #pragma unroll 8
            for (int s = 0; s < TSS; s++) {
                float e = Er1[NTT + s][x];
                a0 += e * eus[k0 + 0][s];
                a1 += e * eus[k0 + 1][s];
                a2 += e * eus[k0 + 2][s];
                a3 += e * eus[k0 + 3][s];
            }
            d_U1t[b][h][k0 + 0][x][a] = a0;
            d_U1t[b][h][k0 + 1][x][a] = a1;
            d_U1t[b][h][k0 + 2][x][a] = a2;
            d_U1t[b][h][k0 + 3][x][a] = a3;
        }
    }
}

// spin until Ssc published (acquire semantics); PURE POLL — no __nanosleep.
// Sleeping warps let the DVFS governor park the clock; polling keeps it up.
__device__ __forceinline__ float spin_ssc(const float* p) {
    float v = ld_acquire_gpu(p);
    while (__float_as_uint(v) == SNAN) {
        v = ld_acquire_gpu(p);
    }
    return v;
}

// per-warp spin + split-weight computation; returns this lane's wspe value,
// writes sref_s (thread tid==0). Ends with a warp fence so every lane's
// subsequent loads are ordered after all lanes' acquires.
__device__ __forceinline__ float warp_wspe(int W, int b, int l, int r,
                                           const float* ownS, float* sref_s,
                                           int tid) {
    int j = tid & 31;
    float v = -1e30f;
    if (j <= W - 2) {
        float sl = (j == 0)     ? 0.f : ownS[j + 1];
        float sr = (j == W - 2) ? 0.f : spin_ssc(&d_Ssc[b][l + 1 + j][r]);
        v = sl + sr;
    }
    float mx = v;
    #pragma unroll
    for (int o = 16; o > 0; o >>= 1) mx = fmaxf(mx, __shfl_xor_sync(0xffffffffu, mx, o));
    float w = (j <= W - 2) ? expf(v - mx) : 0.f;
    if (tid == 0) *sref_s = mx;
    __syncwarp();   // warp-level memory fence: propagate all lanes' acquires
    return w;
}

// ---------------- kernel 2: dataflow chart kernel ----------------
__global__ void __launch_bounds__(THR, 1) k_chart(const float* __restrict__ unary,
                                                  const float* __restrict__ root,
                                                  float* __restrict__ out) {
    extern __shared__ float dyn[];
    float* P0f  = dyn;                       // [24][264] fp32, row = hh, col = sc
    float* P1f  = dyn + 24 * 264;            // [24][264]
    float* ownB = dyn + 2 * 24 * 264;        // [23][16][24] fp32, slot = width-2
    __shared__ float eu_s[Nn][TT];
    __shared__ __align__(16) float wRTi[NTT][24][2];   // [c][jj]{w0, w1} interleaved
    __shared__ float BL2s[NTT][Nn];
    __shared__ float tmpsm[NTT][Nn];
    __shared__ float ownBu[Nn][NTT];   // slot = width-2
    __shared__ float ownS[Nn + 1];     // own Ssc by width
    __shared__ float buR0s[NTT];       // wspe[0]   * betau(l+1, r)
    __shared__ float buLW[NTT];        // wspe[W-2] * ownBu(l, r-1)
    __shared__ unsigned Msm_u;         // cell max as uint (tvals >= 0)
    __shared__ float sref_s;

    int tid = threadIdx.x;
    int b = blockIdx.x / NL;
    int l = blockIdx.x % NL;

    for (int t = tid; t < Nn * TT; t += THR)
        (&eu_s[0][0])[t] = fexp(unary[b * Nn * TT + t]);
    for (int t = tid; t < 8832; t += THR) ownB[t] = 0.f;
    if (tid < 2) ownS[tid] = 0.f;
    if (tid == 32) Msm_u = 0u;
    __syncthreads();

    int Wmax = Nn - l;
    for (int W = 2; W <= Wmax; W++) {
        int r = l + W;
        int nT = NTT * W;
        int a = tid & 15, hh = tid >> 4;
        float wl = 0.f;   // this lane's wspe value (per-warp redundant)

        if (W >= 4) {
            // ======== phase A (no block barrier before it) ========
            wl = warp_wspe(W, b, l, r, ownS, &sref_s, tid);

            // weight tables + boundary child data (uses own-warp wspe via shfl)
            {
                int c = tid / 24, jj = tid % 24;   // THR == 16*24
                int j = jj + 1;
                bool in = (j <= W - 3);
                float wj = __shfl_sync(0xffffffffu, wl, j & 31);
                wRTi[c][jj][0] = in ? wj * __ldcg(&d_betau[b][l + 1 + j][r][c]) : 0.f;
                wRTi[c][jj][1] = in ? wj * ownBu[j - 1][c] : 0.f;
            }
            if (tid < nT) {
                int c2 = tid / W, h2 = tid % W;
                BL2s[c2][h2] = __ldcg(&d_beta[b][l + 1][r][c2][l + h2]);
            }
            if (tid >= 352) {
                float w0  = __shfl_sync(0xffffffffu, wl, 0);
                float wW2 = __shfl_sync(0xffffffffu, wl, W - 2);
                int c = tid - 352;
                if (c < NTT) {
                    buR0s[c] = w0  * __ldcg(&d_betau[b][l + 1][r][c]);
                    buLW[c]  = wW2 * ownBu[W - 3][c];
                }
            }

            // hoisted P-build child loads (need only the acquire, done per-warp)
            u64 bvp[24];
            int phh = tid % W, x = tid / W;
            if (tid < nT) {
                #pragma unroll
                for (int j = 1; j <= 24; j++) {
                    if (j <= W - 3) {
                        float bl = ownB[(j - 1) * 384 + x * 24 + phh];
                        float br = __ldcg(&d_beta[b][l + 1 + j][r][x][l + phh]);
                        bvp[j - 1] = pack2(bl, br);
                    } else bvp[j - 1] = 0ULL;
                }
            }
            __syncthreads();   // bar 1

            // ======== P-build FMA: both tables fused via FFMA2 ========
            if (tid < nT) {
                #pragma unroll
                for (int c = 0; c < NTT; c++) {
                    u64 acc = 0ULL;
                    #pragma unroll
                    for (int k = 0; k < 6; k++) {
                        if (4 * k <= W - 4) {   // warp-uniform
                            const u64* wp = reinterpret_cast<const u64*>(&wRTi[c][4 * k][0]);
                            acc = ffma2(bvp[4 * k + 0], wp[0], acc);
                            acc = ffma2(bvp[4 * k + 1], wp[1], acc);
                            acc = ffma2(bvp[4 * k + 2], wp[2], acc);
                            acc = ffma2(bvp[4 * k + 3], wp[3], acc);
                        }
                    }
                    float2 pv = unpack2(acc);
                    P0f[phh * 264 + x * 16 + c] = pv.x;
                    P1f[phh * 264 + c * 16 + x] = pv.y;
                }
            }
            __syncthreads();   // bar 2

            // ======== contraction + folded boundary + per-warp max ========
            {
                int wd = tid >> 5, lane = tid & 31;
                int sc_lo = lane >> 1, a8 = lane & 1;
                float wspe0  = __shfl_sync(0xffffffffu, wl, 0);
                float wspeW2 = __shfl_sync(0xffffffffu, wl, W - 2);
                float wmax = 0.f;
                for (int chh = wd; chh < W; chh += 12) {
                    const uint4* E0 = reinterpret_cast<const uint4*>(&d_E0h[b][l + chh][0][0]);
                    const uint4* E1 = reinterpret_cast<const uint4*>(&d_E1h[b][l + chh][0][0]);
                    const float* p0 = P0f + chh * 264;
                    const float* p1 = P1f + chh * 264;
                    float acc[8];
                    #pragma unroll
                    for (int k = 0; k < 8; k++) acc[k] = 0.f;
                    #pragma unroll
                    for (int i = 0; i < 16; i++) {
                        int sc = i * 16 + sc_lo;
                        float v0 = p0[sc];
                        float v1 = p1[sc];
                        uint4 e0 = __ldg(E0 + sc * 2 + a8);
                        uint4 e1 = __ldg(E1 + sc * 2 + a8);
                        float2 f;
                        f = __half22float2(*reinterpret_cast<const __half2*>(&e0.x));
                        acc[0] = fmaf(v0, f.x, acc[0]); acc[1] = fmaf(v0, f.y, acc[1]);
                        f = __half22float2(*reinterpret_cast<const __half2*>(&e0.y));
                        acc[2] = fmaf(v0, f.x, acc[2]); acc[3] = fmaf(v0, f.y, acc[3]);
                        f = __half22float2(*reinterpret_cast<const __half2*>(&e0.z));
                        acc[4] = fmaf(v0, f.x, acc[4]); acc[5] = fmaf(v0, f.y, acc[5]);
                        f = __half22float2(*reinterpret_cast<const __half2*>(&e0.w));
                        acc[6] = fmaf(v0, f.x, acc[6]); acc[7] = fmaf(v0, f.y, acc[7]);
                        f = __half22float2(*reinterpret_cast<const __half2*>(&e1.x));
                        acc[0] = fmaf(v1, f.x, acc[0]); acc[1] = fmaf(v1, f.y, acc[1]);
                        f = __half22float2(*reinterpret_cast<const __half2*>(&e1.y));
                        acc[2] = fmaf(v1, f.x, acc[2]); acc[3] = fmaf(v1, f.y, acc[3]);
                        f = __half22float2(*reinterpret_cast<const __half2*>(&e1.z));
                        acc[4] = fmaf(v1, f.x, acc[4]); acc[5] = fmaf(v1, f.y, acc[5]);
                        f = __half22float2(*reinterpret_cast<const __half2*>(&e1.w));
                        acc[6] = fmaf(v1, f.x, acc[6]); acc[7] = fmaf(v1, f.y, acc[7]);
                    }
                    // folded boundary terms (fp32 tables, weights pre-scaled by ESCALE)
                    {   // s2: U1(l+hh, k=l) . (wspe0 * BL2)
                        float v = wspe0 * ESCALE * BL2s[sc_lo][chh];
                        const float4* U1 = reinterpret_cast<const float4*>(
                            &d_U1t[b][l + chh][l][sc_lo][a8 * 8]);
                        float4 ua = __ldg(U1), ub = __ldg(U1 + 1);
                        acc[0] = fmaf(v, ua.x, acc[0]); acc[1] = fmaf(v, ua.y, acc[1]);
                        acc[2] = fmaf(v, ua.z, acc[2]); acc[3] = fmaf(v, ua.w, acc[3]);
                        acc[4] = fmaf(v, ub.x, acc[4]); acc[5] = fmaf(v, ub.y, acc[5]);
                        acc[6] = fmaf(v, ub.z, acc[6]); acc[7] = fmaf(v, ub.w, acc[7]);
                    }
                    {   // s3: U0(l+hh, k=r-1) . (wspeW2 * ownB(l, r-1))
                        float v = wspeW2 * ESCALE * ownB[(W - 3) * 384 + sc_lo * 24 + chh];
                        const float4* U0 = reinterpret_cast<const float4*>(
                            &d_U0t[b][l + chh][r - 1][sc_lo][a8 * 8]);
                        float4 ua = __ldg(U0), ub = __ldg(U0 + 1);
                        acc[0] = fmaf(v, ua.x, acc[0]); acc[1] = fmaf(v, ua.y, acc[1]);
                        acc[2] = fmaf(v, ua.z, acc[2]); acc[3] = fmaf(v, ua.w, acc[3]);
                        acc[4] = fmaf(v, ub.x, acc[4]); acc[5] = fmaf(v, ub.y, acc[5]);
                        acc[6] = fmaf(v, ub.z, acc[6]); acc[7] = fmaf(v, ub.w, acc[7]);
                    }
                    if (chh == 0) {   // s1: V0(l) . buR0s
                        float v = ESCALE * buR0s[sc_lo];
                        const float4* V0 = reinterpret_cast<const float4*>(
                            &d_V0t[b][l][sc_lo][a8 * 8]);
                        float4 ua = __ldg(V0), ub = __ldg(V0 + 1);
                        acc[0] = fmaf(v, ua.x, acc[0]); acc[1] = fmaf(v, ua.y, acc[1]);
                        acc[2] = fmaf(v, ua.z, acc[2]); acc[3] = fmaf(v, ua.w, acc[3]);
                        acc[4] = fmaf(v, ub.x, acc[4]); acc[5] = fmaf(v, ub.y, acc[5]);
                        acc[6] = fmaf(v, ub.z, acc[6]); acc[7] = fmaf(v, ub.w, acc[7]);
                    }
                    if (chh == W - 1) {   // s4: V1(r-1) . buLW
                        float v = ESCALE * buLW[sc_lo];
                        const float4* V1 = reinterpret_cast<const float4*>(
                            &d_V1t[b][r - 1][sc_lo][a8 * 8]);
                        float4 ua = __ldg(V1), ub = __ldg(V1 + 1);
                        acc[0] = fmaf(v, ua.x, acc[0]); acc[1] = fmaf(v, ua.y, acc[1]);
                        acc[2] = fmaf(v, ua.z, acc[2]); acc[3] = fmaf(v, ua.w, acc[3]);
                        acc[4] = fmaf(v, ub.x, acc[4]); acc[5] = fmaf(v, ub.y, acc[5]);
                        acc[6] = fmaf(v, ub.z, acc[6]); acc[7] = fmaf(v, ub.w, acc[7]);
                    }
                    #pragma unroll
                    for (int o = 2; o <= 16; o <<= 1) {
                        #pragma unroll
                        for (int k = 0; k < 8; k++)
                            acc[k] += __shfl_xor_sync(0xffffffffu, acc[k], o);
                    }
                    if (sc_lo == 0) {
                        int abase = a8 * 8;
                        #pragma unroll
                        for (int k = 0; k < 8; k++) {
                            float tv = acc[k] * EINV;
                            tmpsm[abase + k][chh] = tv;
                            wmax = fmaxf(wmax, tv);
                        }
                    }
                }
                wmax = fmaxf(wmax, __shfl_xor_sync(0xffffffffu, wmax, 1));
                if (lane == 0 && wmax > 0.f)
                    atomicMax(reinterpret_cast<int*>(const_cast<unsigned*>(&Msm_u)),
                              (int)__float_as_uint(wmax));
            }
            __syncthreads();   // bar 3
        } else {
            // ======== W == 2 / 3 ========
            float w0 = 1.f, wW2 = 1.f;
            if (W == 3) {
                wl = warp_wspe(W, b, l, r, ownS, &sref_s, tid);
                w0  = __shfl_sync(0xffffffffu, wl, 0);
                wW2 = __shfl_sync(0xffffffffu, wl, W - 2);
                if (tid < nT) {
                    int c2 = tid / W, h2 = tid % W;
                    BL2s[c2][h2] = __ldcg(&d_beta[b][l + 1][r][c2][l + h2]);
                }
                if (tid >= 352) {
                    int c = tid - 352;
                    if (c < NTT) {
                        buR0s[c] = w0  * __ldcg(&d_betau[b][l + 1][r][c]);
                        buLW[c]  = wW2 * ownBu[W - 3][c];
                    }
                }
            } else {
                if (tid == 0) sref_s = 0.f;
            }
            __syncthreads();   // bar 1

            float tval = 0.f;
            if (tid < nT) {
                if (W == 3) {
                    float s2 = 0.f, s3 = 0.f;
                    #pragma unroll
                    for (int c = 0; c < NTT; c++) {
                        s2 += __ldg(&d_U1t[b][l + hh][l][c][a]) * BL2s[c][hh];
                        s3 += __ldg(&d_U0t[b][l + hh][r - 1][c][a]) * ownB[0 * 384 + c * 24 + hh];
                    }
                    tval = w0 * s2 + wW2 * s3;
                    if (hh == 0) {
                        float s1 = 0.f;
                        #pragma unroll
                        for (int c = 0; c < NTT; c++)
                            s1 += __ldg(&d_V0t[b][l][c][a]) * buR0s[c];
                        tval += s1;
                    }
                    if (hh == W - 1) {
                        float s4 = 0.f;
                        #pragma unroll
                        for (int c = 0; c < NTT; c++)
                            s4 += __ldg(&d_V1t[b][r - 1][c][a]) * buLW[c];
                        tval += s4;
                    }
                } else {  // W == 2
                    if (hh == 0) {
                        #pragma unroll 8
                        for (int c = 0; c < TSS; c++)
                            tval += eu_s[l + 1][NTT + c] * __ldg(&d_V0t[b][l][NTT + c][a]);
                    } else {
                        #pragma unroll 8
                        for (int c = 0; c < TSS; c++)
                            tval += eu_s[l][NTT + c] * __ldg(&d_V1t[b][l + 1][NTT + c][a]);
                    }
                }
                tmpsm[a][hh] = tval;
            }
            float wm = tval;
            #pragma unroll
            for (int o = 16; o > 0; o >>= 1) wm = fmaxf(wm, __shfl_xor_sync(0xffffffffu, wm, o));
            if ((tid & 31) == 0 && wm > 0.f)
                atomicMax(reinterpret_cast<int*>(const_cast<unsigned*>(&Msm_u)),
                          (int)__float_as_uint(wm));
            __syncthreads();   // bar 3
        }

        // ======== commit + publish ========
        float Msm = __uint_as_float(Msm_u);
        float invM = 1.f / Msm;
        {
            int ca = tid / Nn, habs = tid % Nn;   // THR == 16*24 exactly
            float v = 0.f;
            if (habs >= l && habs < r) {
                v = tmpsm[ca][habs - l] * invM;
                ownB[(W - 2) * 384 + ca * 24 + (habs - l)] = v;
            }
            __stcg(&d_beta[b][l][r][ca][habs], v);
        }
        if (tid < NTT) {
            float accu = 0.f;
            for (int h2 = 0; h2 < W; h2++)
                accu += tmpsm[tid][h2] * eu_s[l + h2][tid];
            float bu = accu * invM;
            __stcg(&d_betau[b][l][r][tid], bu);
            ownBu[W - 2][tid] = bu;
            if (W == Nn) {   // only block (b, 0): fused root reduction
                float v = bu * __expf(root[b * NTT + tid]);
                #pragma unroll
                for (int o = 8; o > 0; o >>= 1) v += __shfl_xor_sync(0xffffu, v, o);
                if (tid == 0) out[b] = sref_s + logf(Msm) + logf(v);
            }
        }
        float ss = 0.f;
        if (tid == 0) {
            ss = sref_s + logf(Msm);
            ownS[W] = ss;   // written BEFORE bar 4 so all warps may read it next cell
        }
        __syncthreads();   // bar 4: all stores + ownS ordered before release
        if (tid == 0) st_release_gpu(&d_Ssc[b][l][r], ss);
        if (tid == 32) Msm_u = 0u;   // ordered for consumers by next cell's bar 1/2
    }
}

// ---------------- launch ----------------
extern "C" void kernel_launch(void* const* d_in, const int* in_sizes, int n_in,
                              void* d_out, int out_size) {
    const float* unary = nullptr;
    const float* rule  = nullptr;
    const float* root  = nullptr;
    for (int i = 0; i < n_in; i++) {
        if (in_sizes[i] == Bv * Nn * TT)                      unary = (const float*)d_in[i];
        else if (in_sizes[i] == Bv * NTT * Nn * TT * TT * 2)  rule  = (const float*)d_in[i];
        else if (in_sizes[i] == Bv * NTT)                     root  = (const float*)d_in[i];
    }

    int dynBytes = (2 * 24 * 264 + 23 * 16 * 24) * (int)sizeof(float);  // 86016
    cudaFuncSetAttribute(k_chart, cudaFuncAttributeMaxDynamicSharedMemorySize, dynBytes);

    k_pre<<<Bv * NTT * Nn, 256>>>(rule, unary);
    k_chart<<<Bv * NL, THR, dynBytes>>>(unary, root, (float*)d_out);
}